// round 1
// baseline (speedup 1.0000x reference)
#include <cuda_runtime.h>
#include <math.h>

#define N_NODES 20000
#define K_REL   4
#define E_EDGES 320000
#define INDIM   1024
#define HINDIM  256
#define DDIM    128
#define GATEH   128
#define TEMP_INV (1.0f/0.6f)
#define MCLAMP  20.0f

// ---------------- scratch (device globals; no allocation) ----------------
__device__ float g_buf0[N_NODES * HINDIM];
__device__ float g_buf1[N_NODES * HINDIM];
__device__ float g_H[N_NODES * DDIM];
__device__ float g_Z[N_NODES * DDIM];
__device__ float g_M[N_NODES * K_REL * DDIM];
__device__ float g_gateH[N_NODES * GATEH];
__device__ float g_G[N_NODES * K_REL * GATEH];
__device__ float g_scores[N_NODES * K_REL];
__device__ float g_alpha[2 * N_NODES * K_REL];
__device__ float g_Xres[N_NODES * DDIM];
__device__ float g_hid[N_NODES * DDIM];
__device__ float g_colsum[DDIM];
__device__ float g_sumsq[1];
__device__ float g_stats[DDIM + 1];   // mu[128], inv_norm

// ---------------- generic tiled fp32 GEMM: C = A[MxK] @ B[KxN] (+bias)(+relu) ----
// 64x64 tile, 256 threads, 4x4 per thread, BK=16.
template <bool RELU>
__global__ __launch_bounds__(256) void gemm_kernel(
    const float* __restrict__ A, const float* __restrict__ B,
    const float* __restrict__ bias, float* __restrict__ C,
    int M, int K, int N)
{
    __shared__ float As[64][16];
    __shared__ float Bs[16][64];

    int tid = threadIdx.x;
    int tx = tid & 15;       // 0..15 -> col group
    int ty = tid >> 4;       // 0..15 -> row group
    int rowBase = blockIdx.y * 64;
    int colBase = blockIdx.x * 64;

    float acc[4][4];
#pragma unroll
    for (int i = 0; i < 4; i++)
#pragma unroll
        for (int j = 0; j < 4; j++) acc[i][j] = 0.f;

    for (int k0 = 0; k0 < K; k0 += 16) {
        // load A tile 64x16: consecutive threads -> consecutive k (coalesced per 16)
#pragma unroll
        for (int i = tid; i < 64 * 16; i += 256) {
            int r = i >> 4, c = i & 15;
            int gr = rowBase + r;
            As[r][c] = (gr < M) ? A[(long long)gr * K + k0 + c] : 0.f;
        }
        // load B tile 16x64: consecutive threads -> consecutive n (coalesced)
#pragma unroll
        for (int i = tid; i < 16 * 64; i += 256) {
            int r = i >> 6, c = i & 63;
            int gc = colBase + c;
            Bs[r][c] = (gc < N) ? B[(long long)(k0 + r) * N + gc] : 0.f;
        }
        __syncthreads();
#pragma unroll
        for (int kk = 0; kk < 16; kk++) {
            float a0 = As[ty * 4 + 0][kk];
            float a1 = As[ty * 4 + 1][kk];
            float a2 = As[ty * 4 + 2][kk];
            float a3 = As[ty * 4 + 3][kk];
            float4 bv = *reinterpret_cast<const float4*>(&Bs[kk][tx * 4]);
            acc[0][0] += a0 * bv.x; acc[0][1] += a0 * bv.y; acc[0][2] += a0 * bv.z; acc[0][3] += a0 * bv.w;
            acc[1][0] += a1 * bv.x; acc[1][1] += a1 * bv.y; acc[1][2] += a1 * bv.z; acc[1][3] += a1 * bv.w;
            acc[2][0] += a2 * bv.x; acc[2][1] += a2 * bv.y; acc[2][2] += a2 * bv.z; acc[2][3] += a2 * bv.w;
            acc[3][0] += a3 * bv.x; acc[3][1] += a3 * bv.y; acc[3][2] += a3 * bv.z; acc[3][3] += a3 * bv.w;
        }
        __syncthreads();
    }

#pragma unroll
    for (int i = 0; i < 4; i++) {
        int r = rowBase + ty * 4 + i;
        if (r >= M) continue;
#pragma unroll
        for (int j = 0; j < 4; j++) {
            int c = colBase + tx * 4 + j;
            if (c >= N) continue;
            float v = acc[i][j];
            if (bias) v += bias[c];
            if (RELU) v = fmaxf(v, 0.f);
            C[(long long)r * N + c] = v;
        }
    }
}

// ---------------- misc kernels ----------------
__global__ void zero_kernel(float* p, int n) {
    int i = blockIdx.x * blockDim.x + threadIdx.x;
    int stride = gridDim.x * blockDim.x;
    for (; i < n; i += stride) p[i] = 0.f;
}

__global__ void scatter_kernel(const int* __restrict__ rows, const int* __restrict__ cols,
                               const float* __restrict__ Z, float* __restrict__ M)
{
    long long idx = (long long)blockIdx.x * blockDim.x + threadIdx.x;
    int warp = (int)(idx >> 5);
    int lane = (int)(idx & 31);
    if (warp >= K_REL * E_EDGES) return;
    int k = warp / E_EDGES;
    int e = warp - k * E_EDGES;
    int r = rows[k * E_EDGES + e];
    int c = cols[k * E_EDGES + e];
    float4 v = reinterpret_cast<const float4*>(Z + (long long)c * DDIM)[lane];
    float* dst = M + ((long long)r * K_REL + k) * DDIM + lane * 4;
    asm volatile("red.global.add.v4.f32 [%0], {%1,%2,%3,%4};"
                 :: "l"(dst), "f"(v.x), "f"(v.y), "f"(v.z), "f"(v.w) : "memory");
}

__global__ void clip_kernel(float* p, int n) {
    int i = blockIdx.x * blockDim.x + threadIdx.x;
    int stride = gridDim.x * blockDim.x;
    for (; i < n; i += stride) {
        float v = p[i];
        p[i] = fminf(fmaxf(v, -MCLAMP), MCLAMP);
    }
}

// score[n,k] = relu(G[nk]+gateH[n]+logdeg*w_ld+bg1) . Wg2 + bg2 ; one warp per (n,k)
__global__ void score_kernel(const float* __restrict__ G, const float* __restrict__ gateH,
                             const float* __restrict__ logdeg, const float* __restrict__ w_ld,
                             const float* __restrict__ bg1, const float* __restrict__ Wg2,
                             const float* __restrict__ bg2, float* __restrict__ scores)
{
    int warp = (blockIdx.x * blockDim.x + threadIdx.x) >> 5;
    int lane = threadIdx.x & 31;
    if (warp >= N_NODES * K_REL) return;
    int n = warp >> 2;  // K_REL = 4
    float ld = logdeg[warp];
    float acc = 0.f;
#pragma unroll
    for (int i = 0; i < 4; i++) {
        int d = lane + i * 32;
        float v = G[(long long)warp * GATEH + d] + gateH[(long long)n * GATEH + d]
                + ld * w_ld[d] + bg1[d];
        v = fmaxf(v, 0.f);
        acc += v * Wg2[d];
    }
#pragma unroll
    for (int o = 16; o > 0; o >>= 1) acc += __shfl_xor_sync(0xFFFFFFFFu, acc, o);
    if (lane == 0) scores[warp] = acc + bg2[0];
}

__global__ void softmax_kernel(const float* __restrict__ scores, const float* __restrict__ mask,
                               float* __restrict__ alpha)
{
    int n = blockIdx.x * blockDim.x + threadIdx.x;
    if (n >= N_NODES) return;
    float s[K_REL], a[K_REL];
    float m = -1e30f;
#pragma unroll
    for (int k = 0; k < K_REL; k++) { s[k] = scores[n * K_REL + k] * TEMP_INV; m = fmaxf(m, s[k]); }
    float sum = 0.f;
#pragma unroll
    for (int k = 0; k < K_REL; k++) { a[k] = __expf(s[k] - m); sum += a[k]; }
    float inv = 1.f / sum;
    float sum2 = 0.f;
#pragma unroll
    for (int k = 0; k < K_REL; k++) { a[k] = a[k] * inv * mask[n * K_REL + k]; sum2 += a[k]; }
    float inv2 = 1.f / fmaxf(sum2, 1e-12f);
    float sum3 = 0.f;
#pragma unroll
    for (int k = 0; k < K_REL; k++) { a[k] = fmaxf(a[k] * inv2, 1e-8f); sum3 += a[k]; }
    float inv3 = 1.f / fmaxf(sum3, 1e-12f);
#pragma unroll
    for (int k = 0; k < K_REL; k++) alpha[n * K_REL + k] = a[k] * inv3;
}

// fused = sum_k alpha*M ; x = fused + H ; accumulate colsum & sumsq. 1 block = 1 node, 128 thr.
__global__ void fused_kernel(const float* __restrict__ M, const float* __restrict__ alpha,
                             const float* __restrict__ H, float* __restrict__ Xres,
                             float* __restrict__ colsum, float* __restrict__ sumsq)
{
    int n = blockIdx.x;
    int d = threadIdx.x;
    __shared__ float a[K_REL];
    __shared__ float wsum[4];
    if (d < K_REL) a[d] = alpha[n * K_REL + d];
    __syncthreads();
    float f = 0.f;
#pragma unroll
    for (int k = 0; k < K_REL; k++) f += a[k] * M[((long long)n * K_REL + k) * DDIM + d];
    float x = f + H[(long long)n * DDIM + d];
    Xres[(long long)n * DDIM + d] = x;
    atomicAdd(&colsum[d], x);
    float q = x * x;
#pragma unroll
    for (int o = 16; o > 0; o >>= 1) q += __shfl_xor_sync(0xFFFFFFFFu, q, o);
    if ((d & 31) == 0) wsum[d >> 5] = q;
    __syncthreads();
    if (d == 0) atomicAdd(sumsq, wsum[0] + wsum[1] + wsum[2] + wsum[3]);
}

__global__ void stats_kernel(const float* __restrict__ colsum, const float* __restrict__ sumsq,
                             float* __restrict__ stats)
{
    int d = threadIdx.x;  // 128 threads
    __shared__ float wsum[4];
    float mu = colsum[d] * (1.0f / N_NODES);
    stats[d] = mu;
    float q = mu * mu;
#pragma unroll
    for (int o = 16; o > 0; o >>= 1) q += __shfl_xor_sync(0xFFFFFFFFu, q, o);
    if ((d & 31) == 0) wsum[d >> 5] = q;
    __syncthreads();
    if (d == 0) {
        float summu2 = wsum[0] + wsum[1] + wsum[2] + wsum[3];
        float var = (sumsq[0] - (float)N_NODES * summu2) * (1.0f / N_NODES);
        var = fmaxf(var, 0.f);
        stats[DDIM] = 1.0f / (sqrtf(var) + 1e-6f);
    }
}

__global__ void normalize_kernel(const float* __restrict__ Xres, const float* __restrict__ stats,
                                 float* __restrict__ H)
{
    int i = blockIdx.x * blockDim.x + threadIdx.x;
    if (i >= N_NODES * DDIM) return;
    int d = i & (DDIM - 1);
    float v = (Xres[i] - stats[d]) * stats[DDIM];
    H[i] = fmaxf(v, 0.f);
}

// logits[n] = hid[n] . Wh2 + bh2 ; one warp per node
__global__ void logits_kernel(const float* __restrict__ hid, const float* __restrict__ Wh2,
                              const float* __restrict__ bh2, float* __restrict__ out)
{
    int warp = (blockIdx.x * blockDim.x + threadIdx.x) >> 5;
    int lane = threadIdx.x & 31;
    if (warp >= N_NODES) return;
    float acc = 0.f;
#pragma unroll
    for (int i = 0; i < 4; i++) {
        int d = lane + i * 32;
        acc += hid[(long long)warp * DDIM + d] * Wh2[d];
    }
#pragma unroll
    for (int o = 16; o > 0; o >>= 1) acc += __shfl_xor_sync(0xFFFFFFFFu, acc, o);
    if (lane == 0) out[warp] = acc + bh2[0];
}

__global__ void copy_alpha_kernel(const float* __restrict__ alpha, float* __restrict__ out,
                                  int out_size)
{
    int i = blockIdx.x * blockDim.x + threadIdx.x;
    if (i >= 2 * N_NODES * K_REL) return;
    if (N_NODES + i < out_size) out[N_NODES + i] = alpha[i];
}

// ---------------- host ----------------
static inline dim3 gemm_grid(int M, int N) { return dim3((N + 63) / 64, (M + 63) / 64); }

extern "C" void kernel_launch(void* const* d_in, const int* in_sizes, int n_in,
                              void* d_out, int out_size)
{
    const float* X      = (const float*)d_in[0];
    const int*   rows   = (const int*)d_in[1];
    const int*   cols   = (const int*)d_in[2];
    const float* mask   = (const float*)d_in[3];
    const float* logdeg = (const float*)d_in[4];
    const float* W_in0  = (const float*)d_in[5];
    const float* b_in0  = (const float*)d_in[6];
    const float* W_in1  = (const float*)d_in[7];
    const float* b_in1  = (const float*)d_in[8];
    const float* W_in2  = (const float*)d_in[9];
    const float* b_in2  = (const float*)d_in[10];
    const float* Wmsg[2]  = {(const float*)d_in[11], (const float*)d_in[16]};
    const float* Wg1[2]   = {(const float*)d_in[12], (const float*)d_in[17]};
    const float* bg1[2]   = {(const float*)d_in[13], (const float*)d_in[18]};
    const float* Wg2[2]   = {(const float*)d_in[14], (const float*)d_in[19]};
    const float* bg2[2]   = {(const float*)d_in[15], (const float*)d_in[20]};
    const float* Wh1    = (const float*)d_in[21];
    const float* bh1    = (const float*)d_in[22];
    const float* Wh2    = (const float*)d_in[23];
    const float* bh2    = (const float*)d_in[24];
    float* out = (float*)d_out;

    float *buf0, *buf1, *H, *Z, *M, *gateH, *G, *scores, *alpha, *Xres, *hid, *colsum, *sumsq, *stats;
    cudaGetSymbolAddress((void**)&buf0,  g_buf0);
    cudaGetSymbolAddress((void**)&buf1,  g_buf1);
    cudaGetSymbolAddress((void**)&H,     g_H);
    cudaGetSymbolAddress((void**)&Z,     g_Z);
    cudaGetSymbolAddress((void**)&M,     g_M);
    cudaGetSymbolAddress((void**)&gateH, g_gateH);
    cudaGetSymbolAddress((void**)&G,     g_G);
    cudaGetSymbolAddress((void**)&scores,g_scores);
    cudaGetSymbolAddress((void**)&alpha, g_alpha);
    cudaGetSymbolAddress((void**)&Xres,  g_Xres);
    cudaGetSymbolAddress((void**)&hid,   g_hid);
    cudaGetSymbolAddress((void**)&colsum,g_colsum);
    cudaGetSymbolAddress((void**)&sumsq, g_sumsq);
    cudaGetSymbolAddress((void**)&stats, g_stats);

    // ---- encoder: H = relu(relu(relu(X W0 + b0) W1 + b1) W2 + b2)
    gemm_kernel<true><<<gemm_grid(N_NODES, HINDIM), 256>>>(X,    W_in0, b_in0, buf0, N_NODES, INDIM,  HINDIM);
    gemm_kernel<true><<<gemm_grid(N_NODES, HINDIM), 256>>>(buf0, W_in1, b_in1, buf1, N_NODES, HINDIM, HINDIM);
    gemm_kernel<true><<<gemm_grid(N_NODES, DDIM),   256>>>(buf1, W_in2, b_in2, H,    N_NODES, HINDIM, DDIM);

    const int mElems = N_NODES * K_REL * DDIM;
    const int scatterWarps = K_REL * E_EDGES;
    const int scatterBlocks = (scatterWarps * 32 + 255) / 256;

    for (int b = 0; b < 2; b++) {
        // Z = H @ Wmsg
        gemm_kernel<false><<<gemm_grid(N_NODES, DDIM), 256>>>(H, Wmsg[b], nullptr, Z, N_NODES, DDIM, DDIM);
        // M = segment scatter
        zero_kernel<<<4096, 256>>>(M, mElems);
        scatter_kernel<<<scatterBlocks, 256>>>(rows, cols, Z, M);
        clip_kernel<<<4096, 256>>>(M, mElems);
        // gate: gateH = H @ Wg1[0:128], G = Mflat @ Wg1[128:256]
        gemm_kernel<false><<<gemm_grid(N_NODES, GATEH), 256>>>(H, Wg1[b], nullptr, gateH, N_NODES, DDIM, GATEH);
        gemm_kernel<false><<<gemm_grid(N_NODES * K_REL, GATEH), 256>>>(M, Wg1[b] + 128 * GATEH, nullptr, G,
                                                                       N_NODES * K_REL, DDIM, GATEH);
        score_kernel<<<(N_NODES * K_REL * 32 + 255) / 256, 256>>>(G, gateH, logdeg, Wg1[b] + 256 * GATEH,
                                                                  bg1[b], Wg2[b], bg2[b], scores);
        softmax_kernel<<<(N_NODES + 255) / 256, 256>>>(scores, mask, alpha + b * N_NODES * K_REL);
        // fused + residual + pairnorm
        zero_kernel<<<1, 256>>>(colsum, DDIM);
        zero_kernel<<<1, 32>>>(sumsq, 1);
        fused_kernel<<<N_NODES, DDIM>>>(M, alpha + b * N_NODES * K_REL, H, Xres, colsum, sumsq);
        stats_kernel<<<1, DDIM>>>(colsum, sumsq, stats);
        normalize_kernel<<<(N_NODES * DDIM + 255) / 256, 256>>>(Xres, stats, H);
    }

    // ---- head (H >= 0 so relu(H) = H)
    gemm_kernel<true><<<gemm_grid(N_NODES, DDIM), 256>>>(H, Wh1, bh1, hid, N_NODES, DDIM, DDIM);
    logits_kernel<<<(N_NODES * 32 + 255) / 256, 256>>>(hid, Wh2, bh2, out);
    copy_alpha_kernel<<<(2 * N_NODES * K_REL + 255) / 256, 256>>>(alpha, out, out_size);
}

// round 3
// speedup vs baseline: 1.3928x; 1.3928x over previous
#include <cuda_runtime.h>
#include <cuda_bf16.h>
#include <math.h>
#include <cstdint>

#define N_NODES 20000
#define K_REL   4
#define E_EDGES 320000
#define INDIM   1024
#define HINDIM  256
#define DDIM    128
#define GATEH   128
#define TEMP_INV (1.0f/0.6f)
#define MCLAMP  20.0f

// ---------------- scratch (device globals; no allocation) ----------------
__device__ float g_buf0[N_NODES * HINDIM];
__device__ float g_buf1[N_NODES * HINDIM];
__device__ float g_H[N_NODES * DDIM];
__device__ float g_Z[N_NODES * DDIM];
__device__ float g_M[N_NODES * K_REL * DDIM];
__device__ float g_gateH[N_NODES * GATEH];
__device__ float g_G[N_NODES * K_REL * GATEH];
__device__ float g_scores[N_NODES * K_REL];
__device__ float g_alpha[2 * N_NODES * K_REL];
__device__ float g_Xres[N_NODES * DDIM];
__device__ float g_hid[N_NODES * DDIM];
__device__ float g_colsum[DDIM];
__device__ float g_sumsq[1];
__device__ float g_stats[DDIM + 1];
// transposed weights [N, K] K-major
__device__ float g_Wt0[HINDIM * INDIM];
__device__ float g_Wt1[HINDIM * HINDIM];
__device__ float g_Wt2[DDIM * HINDIM];
__device__ float g_WmT[2][DDIM * DDIM];
__device__ float g_Wg1hT[2][GATEH * DDIM];
__device__ float g_Wg1mT[2][GATEH * DDIM];
__device__ float g_Wh1T[DDIM * DDIM];

// ================= baseline-ISA tensor-core helpers =================
__device__ __forceinline__ uint32_t smem_u32(const void* p) {
    uint32_t a;
    asm("{ .reg .u64 t; cvta.to.shared.u64 t, %1; cvt.u32.u64 %0, t; }" : "=r"(a) : "l"(p));
    return a;
}
__device__ __forceinline__ void ldsm_x4(uint32_t* r, uint32_t addr) {
    asm volatile("ldmatrix.sync.aligned.m8n8.x4.shared.b16 {%0,%1,%2,%3}, [%4];"
        : "=r"(r[0]), "=r"(r[1]), "=r"(r[2]), "=r"(r[3]) : "r"(addr));
}
__device__ __forceinline__ void mma_bf16(float* c, const uint32_t* a, const uint32_t* b) {
    asm volatile("mma.sync.aligned.m16n8k16.row.col.f32.bf16.bf16.f32 "
        "{%0,%1,%2,%3}, {%4,%5,%6,%7}, {%8,%9}, {%0,%1,%2,%3};"
        : "+f"(c[0]), "+f"(c[1]), "+f"(c[2]), "+f"(c[3])
        : "r"(a[0]), "r"(a[1]), "r"(a[2]), "r"(a[3]), "r"(b[0]), "r"(b[1]));
}
__device__ __forceinline__ uint32_t pack_bf16(float a, float b) {
    __nv_bfloat162 h = __floats2bfloat162_rn(a, b);
    return *reinterpret_cast<uint32_t*>(&h);
}

// ================= bf16 3-split tensor-core GEMM =================
// C[M,N] = A[M,K] @ Bt[N,K]^T (+bias)(+relu)(clipA). BM=BN=128, BK=32.
// SMEM per stage: Ahi | Alo | Bhi | Blo, each 128 rows x 40 bf16 (80B rows).
#define ROWB 80
#define TILE_B (128 * ROWB)            // 10240
#define STAGE_B (4 * TILE_B)           // 40960
#define GEMM_SMEM (2 * STAGE_B)        // 81920

template <bool RELU, bool BIAS, bool CLIPA>
__global__ __launch_bounds__(256) void mma_gemm(
    const float* __restrict__ A, const float* __restrict__ Bt,
    const float* __restrict__ bias, float* __restrict__ C,
    int M, int K, int N)
{
    extern __shared__ __align__(128) char smem[];
    const int tid = threadIdx.x;
    const int lane = tid & 31;
    const int wid = tid >> 5;
    const int warp_m = wid & 3;        // 4 warps over M
    const int warp_n = wid >> 2;       // 2 warps over N
    const int rowBase = blockIdx.y * 128;
    const int colBase = blockIdx.x * 128;
    const int nch = K >> 5;

    float acc[2][8][4];
#pragma unroll
    for (int i = 0; i < 2; i++)
#pragma unroll
        for (int j = 0; j < 8; j++)
#pragma unroll
            for (int q = 0; q < 4; q++) acc[i][j][q] = 0.f;

    // per-lane ldmatrix base addresses
    const uint32_t sb = smem_u32(smem);
    const int aRow = warp_m * 32 + (lane & 7) + ((lane >> 3) & 1) * 8;
    const int aK   = ((lane >> 4) & 1) * 8;
    const int bRow = warp_n * 64 + (lane & 7) + ((lane >> 4) & 1) * 8;
    const int bK   = ((lane >> 3) & 1) * 8;
    const uint32_t aBase = sb + (uint32_t)(aRow * ROWB + aK * 2);
    const uint32_t bBase = sb + 2u * TILE_B + (uint32_t)(bRow * ROWB + bK * 2);

    float4 aR[4], bR[4];

    // ---- load chunk c into registers
    auto gload = [&](int c) {
        const int k0 = c << 5;
#pragma unroll
        for (int j = 0; j < 4; j++) {
            int idx = tid + j * 256;
            int r = idx >> 3;
            int col = (idx & 7) * 4;
            int gr = rowBase + r;
            float4 v = make_float4(0.f, 0.f, 0.f, 0.f);
            if (gr < M) v = *reinterpret_cast<const float4*>(A + (size_t)gr * K + k0 + col);
            if (CLIPA) {
                v.x = fminf(fmaxf(v.x, -MCLAMP), MCLAMP);
                v.y = fminf(fmaxf(v.y, -MCLAMP), MCLAMP);
                v.z = fminf(fmaxf(v.z, -MCLAMP), MCLAMP);
                v.w = fminf(fmaxf(v.w, -MCLAMP), MCLAMP);
            }
            aR[j] = v;
            bR[j] = *reinterpret_cast<const float4*>(Bt + (size_t)(colBase + r) * K + k0 + col);
        }
    };
    // ---- split + store registers into stage s
    auto sstore = [&](int s) {
        char* st = smem + s * STAGE_B;
#pragma unroll
        for (int j = 0; j < 4; j++) {
            int idx = tid + j * 256;
            int r = idx >> 3;
            int col = (idx & 7) * 4;
            int off = r * ROWB + col * 2;
            float4 v = aR[j];
            float hx = __bfloat162float(__float2bfloat16(v.x));
            float hy = __bfloat162float(__float2bfloat16(v.y));
            float hz = __bfloat162float(__float2bfloat16(v.z));
            float hw = __bfloat162float(__float2bfloat16(v.w));
            *reinterpret_cast<uint2*>(st + off) =
                make_uint2(pack_bf16(hx, hy), pack_bf16(hz, hw));
            *reinterpret_cast<uint2*>(st + TILE_B + off) =
                make_uint2(pack_bf16(v.x - hx, v.y - hy), pack_bf16(v.z - hz, v.w - hw));
            float4 w = bR[j];
            float gx = __bfloat162float(__float2bfloat16(w.x));
            float gy = __bfloat162float(__float2bfloat16(w.y));
            float gz = __bfloat162float(__float2bfloat16(w.z));
            float gw = __bfloat162float(__float2bfloat16(w.w));
            *reinterpret_cast<uint2*>(st + 2 * TILE_B + off) =
                make_uint2(pack_bf16(gx, gy), pack_bf16(gz, gw));
            *reinterpret_cast<uint2*>(st + 3 * TILE_B + off) =
                make_uint2(pack_bf16(w.x - gx, w.y - gy), pack_bf16(w.z - gz, w.w - gw));
        }
    };

    gload(0);
    sstore(0);
    __syncthreads();

    for (int c = 0; c < nch; c++) {
        const int s = c & 1;
        const uint32_t stoff = (uint32_t)s * STAGE_B;
        if (c + 1 < nch) gload(c + 1);

#pragma unroll
        for (int ks = 0; ks < 2; ks++) {
            uint32_t ah[2][4], al[2][4], bh[4][4], bl[4][4];
#pragma unroll
            for (int mt = 0; mt < 2; mt++) {
                ldsm_x4(ah[mt], aBase + stoff + mt * 16 * ROWB + ks * 32);
                ldsm_x4(al[mt], aBase + stoff + TILE_B + mt * 16 * ROWB + ks * 32);
            }
#pragma unroll
            for (int p = 0; p < 4; p++) {
                ldsm_x4(bh[p], bBase + stoff + p * 16 * ROWB + ks * 32);
                ldsm_x4(bl[p], bBase + stoff + TILE_B + p * 16 * ROWB + ks * 32);
            }
#pragma unroll
            for (int mt = 0; mt < 2; mt++) {
#pragma unroll
                for (int nt = 0; nt < 8; nt++) {
                    const uint32_t* bhp = &bh[nt >> 1][(nt & 1) * 2];
                    const uint32_t* blp = &bl[nt >> 1][(nt & 1) * 2];
                    mma_bf16(acc[mt][nt], ah[mt], bhp);
                    mma_bf16(acc[mt][nt], ah[mt], blp);
                    mma_bf16(acc[mt][nt], al[mt], bhp);
                }
            }
        }
        if (c + 1 < nch) sstore((c + 1) & 1);
        __syncthreads();
    }

    // ---- epilogue: direct register stores
    const int g = lane >> 2;
    const int tc2 = (lane & 3) * 2;
#pragma unroll
    for (int mt = 0; mt < 2; mt++) {
#pragma unroll
        for (int nt = 0; nt < 8; nt++) {
            int row0 = rowBase + warp_m * 32 + mt * 16 + g;
            int col = colBase + warp_n * 64 + nt * 8 + tc2;
            float c0 = acc[mt][nt][0], c1 = acc[mt][nt][1];
            float c2 = acc[mt][nt][2], c3 = acc[mt][nt][3];
            if (BIAS) {
                float2 bb = *reinterpret_cast<const float2*>(bias + col);
                c0 += bb.x; c1 += bb.y; c2 += bb.x; c3 += bb.y;
            }
            if (RELU) {
                c0 = fmaxf(c0, 0.f); c1 = fmaxf(c1, 0.f);
                c2 = fmaxf(c2, 0.f); c3 = fmaxf(c3, 0.f);
            }
            if (row0 < M)
                *reinterpret_cast<float2*>(C + (size_t)row0 * N + col) = make_float2(c0, c1);
            if (row0 + 8 < M)
                *reinterpret_cast<float2*>(C + (size_t)(row0 + 8) * N + col) = make_float2(c2, c3);
        }
    }
}

// ================= transpose: Wt[n*K+k] = W[k*N+n] =================
__global__ void transpose_kernel(const float* __restrict__ W, float* __restrict__ Wt, int K, int N)
{
    __shared__ float t[32][33];
    int k0 = blockIdx.y * 32, n0 = blockIdx.x * 32;
    int tx = threadIdx.x, ty = threadIdx.y;
    for (int i = ty; i < 32; i += 8) {
        int k = k0 + i, n = n0 + tx;
        t[i][tx] = (k < K && n < N) ? W[(size_t)k * N + n] : 0.f;
    }
    __syncthreads();
    for (int i = ty; i < 32; i += 8) {
        int n = n0 + i, k = k0 + tx;
        if (n < N && k < K) Wt[(size_t)n * K + k] = t[tx][i];
    }
}

// ================= misc kernels =================
__global__ void zero_kernel(float* p, int n) {
    int i = blockIdx.x * blockDim.x + threadIdx.x;
    int stride = gridDim.x * blockDim.x;
    for (; i < n; i += stride) p[i] = 0.f;
}

__global__ void scatter_kernel(const int* __restrict__ rows, const int* __restrict__ cols,
                               const float* __restrict__ Z, float* __restrict__ Mb)
{
    long long idx = (long long)blockIdx.x * blockDim.x + threadIdx.x;
    int warp = (int)(idx >> 5);
    int lane = (int)(idx & 31);
    if (warp >= K_REL * E_EDGES) return;
    int k = warp / E_EDGES;
    int e = warp - k * E_EDGES;
    int r = rows[k * E_EDGES + e];
    int c = cols[k * E_EDGES + e];
    float4 v = reinterpret_cast<const float4*>(Z + (long long)c * DDIM)[lane];
    float* dst = Mb + ((long long)r * K_REL + k) * DDIM + lane * 4;
    asm volatile("red.global.add.v4.f32 [%0], {%1,%2,%3,%4};"
                 :: "l"(dst), "f"(v.x), "f"(v.y), "f"(v.z), "f"(v.w) : "memory");
}

__global__ void score_kernel(const float* __restrict__ G, const float* __restrict__ gateH,
                             const float* __restrict__ logdeg, const float* __restrict__ w_ld,
                             const float* __restrict__ bg1, const float* __restrict__ Wg2,
                             const float* __restrict__ bg2, float* __restrict__ scores)
{
    int warp = (blockIdx.x * blockDim.x + threadIdx.x) >> 5;
    int lane = threadIdx.x & 31;
    if (warp >= N_NODES * K_REL) return;
    int n = warp >> 2;
    float ld = logdeg[warp];
    float acc = 0.f;
#pragma unroll
    for (int i = 0; i < 4; i++) {
        int d = lane + i * 32;
        float v = G[(long long)warp * GATEH + d] + gateH[(long long)n * GATEH + d]
                + ld * w_ld[d] + bg1[d];
        v = fmaxf(v, 0.f);
        acc += v * Wg2[d];
    }
#pragma unroll
    for (int o = 16; o > 0; o >>= 1) acc += __shfl_xor_sync(0xFFFFFFFFu, acc, o);
    if (lane == 0) scores[warp] = acc + bg2[0];
}

__global__ void softmax_kernel(const float* __restrict__ scores, const float* __restrict__ mask,
                               float* __restrict__ alpha)
{
    int n = blockIdx.x * blockDim.x + threadIdx.x;
    if (n >= N_NODES) return;
    float s[K_REL], a[K_REL];
    float m = -1e30f;
#pragma unroll
    for (int k = 0; k < K_REL; k++) { s[k] = scores[n * K_REL + k] * TEMP_INV; m = fmaxf(m, s[k]); }
    float sum = 0.f;
#pragma unroll
    for (int k = 0; k < K_REL; k++) { a[k] = __expf(s[k] - m); sum += a[k]; }
    float inv = 1.f / sum;
    float sum2 = 0.f;
#pragma unroll
    for (int k = 0; k < K_REL; k++) { a[k] = a[k] * inv * mask[n * K_REL + k]; sum2 += a[k]; }
    float inv2 = 1.f / fmaxf(sum2, 1e-12f);
    float sum3 = 0.f;
#pragma unroll
    for (int k = 0; k < K_REL; k++) { a[k] = fmaxf(a[k] * inv2, 1e-8f); sum3 += a[k]; }
    float inv3 = 1.f / fmaxf(sum3, 1e-12f);
#pragma unroll
    for (int k = 0; k < K_REL; k++) alpha[n * K_REL + k] = a[k] * inv3;
}

__global__ void fused_kernel(const float* __restrict__ Mb, const float* __restrict__ alpha,
                             const float* __restrict__ H, float* __restrict__ Xres,
                             float* __restrict__ colsum, float* __restrict__ sumsq)
{
    int n = blockIdx.x;
    int d = threadIdx.x;
    __shared__ float a[K_REL];
    __shared__ float wsum[4];
    if (d < K_REL) a[d] = alpha[n * K_REL + d];
    __syncthreads();
    float f = 0.f;
#pragma unroll
    for (int k = 0; k < K_REL; k++) {
        float mv = Mb[((long long)n * K_REL + k) * DDIM + d];
        mv = fminf(fmaxf(mv, -MCLAMP), MCLAMP);
        f += a[k] * mv;
    }
    float x = f + H[(long long)n * DDIM + d];
    Xres[(long long)n * DDIM + d] = x;
    atomicAdd(&colsum[d], x);
    float q = x * x;
#pragma unroll
    for (int o = 16; o > 0; o >>= 1) q += __shfl_xor_sync(0xFFFFFFFFu, q, o);
    if ((d & 31) == 0) wsum[d >> 5] = q;
    __syncthreads();
    if (d == 0) atomicAdd(sumsq, wsum[0] + wsum[1] + wsum[2] + wsum[3]);
}

__global__ void stats_kernel(const float* __restrict__ colsum, const float* __restrict__ sumsq,
                             float* __restrict__ stats)
{
    int d = threadIdx.x;
    __shared__ float wsum[4];
    float mu = colsum[d] * (1.0f / N_NODES);
    stats[d] = mu;
    float q = mu * mu;
#pragma unroll
    for (int o = 16; o > 0; o >>= 1) q += __shfl_xor_sync(0xFFFFFFFFu, q, o);
    if ((d & 31) == 0) wsum[d >> 5] = q;
    __syncthreads();
    if (d == 0) {
        float summu2 = wsum[0] + wsum[1] + wsum[2] + wsum[3];
        float var = (sumsq[0] - (float)N_NODES * summu2) * (1.0f / N_NODES);
        var = fmaxf(var, 0.f);
        stats[DDIM] = 1.0f / (sqrtf(var) + 1e-6f);
    }
}

__global__ void normalize_kernel(const float* __restrict__ Xres, const float* __restrict__ stats,
                                 float* __restrict__ H)
{
    int i = blockIdx.x * blockDim.x + threadIdx.x;
    if (i >= N_NODES * DDIM) return;
    int d = i & (DDIM - 1);
    float v = (Xres[i] - stats[d]) * stats[DDIM];
    H[i] = fmaxf(v, 0.f);
}

__global__ void logits_kernel(const float* __restrict__ hid, const float* __restrict__ Wh2,
                              const float* __restrict__ bh2, float* __restrict__ out)
{
    int warp = (blockIdx.x * blockDim.x + threadIdx.x) >> 5;
    int lane = threadIdx.x & 31;
    if (warp >= N_NODES) return;
    float acc = 0.f;
#pragma unroll
    for (int i = 0; i < 4; i++) {
        int d = lane + i * 32;
        acc += hid[(long long)warp * DDIM + d] * Wh2[d];
    }
#pragma unroll
    for (int o = 16; o > 0; o >>= 1) acc += __shfl_xor_sync(0xFFFFFFFFu, acc, o);
    if (lane == 0) out[warp] = acc + bh2[0];
}

__global__ void copy_alpha_kernel(const float* __restrict__ alpha, float* __restrict__ out,
                                  int out_size)
{
    int i = blockIdx.x * blockDim.x + threadIdx.x;
    if (i >= 2 * N_NODES * K_REL) return;
    if (N_NODES + i < out_size) out[N_NODES + i] = alpha[i];
}

// ================= host =================
extern "C" void kernel_launch(void* const* d_in, const int* in_sizes, int n_in,
                              void* d_out, int out_size)
{
    const float* X      = (const float*)d_in[0];
    const int*   rows   = (const int*)d_in[1];
    const int*   cols   = (const int*)d_in[2];
    const float* mask   = (const float*)d_in[3];
    const float* logdeg = (const float*)d_in[4];
    const float* W_in0  = (const float*)d_in[5];
    const float* b_in0  = (const float*)d_in[6];
    const float* W_in1  = (const float*)d_in[7];
    const float* b_in1  = (const float*)d_in[8];
    const float* W_in2  = (const float*)d_in[9];
    const float* b_in2  = (const float*)d_in[10];
    const float* Wmsg[2]  = {(const float*)d_in[11], (const float*)d_in[16]};
    const float* Wg1[2]   = {(const float*)d_in[12], (const float*)d_in[17]};
    const float* bg1[2]   = {(const float*)d_in[13], (const float*)d_in[18]};
    const float* Wg2[2]   = {(const float*)d_in[14], (const float*)d_in[19]};
    const float* bg2[2]   = {(const float*)d_in[15], (const float*)d_in[20]};
    const float* Wh1    = (const float*)d_in[21];
    const float* bh1    = (const float*)d_in[22];
    const float* Wh2    = (const float*)d_in[23];
    const float* bh2    = (const float*)d_in[24];
    float* out = (float*)d_out;

    float *buf0, *buf1, *H, *Z, *Mb, *gateH, *G, *scores, *alpha, *Xres, *hid, *colsum, *sumsq, *stats;
    float *Wt0, *Wt1, *Wt2, *WmT, *Wg1hT, *Wg1mT, *Wh1T;
    cudaGetSymbolAddress((void**)&buf0,  g_buf0);
    cudaGetSymbolAddress((void**)&buf1,  g_buf1);
    cudaGetSymbolAddress((void**)&H,     g_H);
    cudaGetSymbolAddress((void**)&Z,     g_Z);
    cudaGetSymbolAddress((void**)&Mb,    g_M);
    cudaGetSymbolAddress((void**)&gateH, g_gateH);
    cudaGetSymbolAddress((void**)&G,     g_G);
    cudaGetSymbolAddress((void**)&scores,g_scores);
    cudaGetSymbolAddress((void**)&alpha, g_alpha);
    cudaGetSymbolAddress((void**)&Xres,  g_Xres);
    cudaGetSymbolAddress((void**)&hid,   g_hid);
    cudaGetSymbolAddress((void**)&colsum,g_colsum);
    cudaGetSymbolAddress((void**)&sumsq, g_sumsq);
    cudaGetSymbolAddress((void**)&stats, g_stats);
    cudaGetSymbolAddress((void**)&Wt0,   g_Wt0);
    cudaGetSymbolAddress((void**)&Wt1,   g_Wt1);
    cudaGetSymbolAddress((void**)&Wt2,   g_Wt2);
    cudaGetSymbolAddress((void**)&WmT,   g_WmT);
    cudaGetSymbolAddress((void**)&Wg1hT, g_Wg1hT);
    cudaGetSymbolAddress((void**)&Wg1mT, g_Wg1mT);
    cudaGetSymbolAddress((void**)&Wh1T,  g_Wh1T);

    cudaFuncSetAttribute(mma_gemm<true,true,false>,   cudaFuncAttributeMaxDynamicSharedMemorySize, GEMM_SMEM);
    cudaFuncSetAttribute(mma_gemm<false,false,false>, cudaFuncAttributeMaxDynamicSharedMemorySize, GEMM_SMEM);
    cudaFuncSetAttribute(mma_gemm<false,false,true>,  cudaFuncAttributeMaxDynamicSharedMemorySize, GEMM_SMEM);

    dim3 tb(32, 8);
    transpose_kernel<<<dim3(8, 32), tb>>>(W_in0, Wt0, INDIM, HINDIM);
    transpose_kernel<<<dim3(8, 8),  tb>>>(W_in1, Wt1, HINDIM, HINDIM);
    transpose_kernel<<<dim3(4, 8),  tb>>>(W_in2, Wt2, HINDIM, DDIM);
    for (int b = 0; b < 2; b++) {
        transpose_kernel<<<dim3(4, 4), tb>>>(Wmsg[b], WmT + b * DDIM * DDIM, DDIM, DDIM);
        transpose_kernel<<<dim3(4, 4), tb>>>(Wg1[b], Wg1hT + b * GATEH * DDIM, DDIM, GATEH);
        transpose_kernel<<<dim3(4, 4), tb>>>(Wg1[b] + DDIM * GATEH, Wg1mT + b * GATEH * DDIM, DDIM, GATEH);
    }
    transpose_kernel<<<dim3(4, 4), tb>>>(Wh1, Wh1T, DDIM, DDIM);

    const int MT = (N_NODES + 127) / 128;  // 157

    // encoder
    mma_gemm<true,true,false><<<dim3(2, MT), 256, GEMM_SMEM>>>(X,    Wt0, b_in0, buf0, N_NODES, INDIM,  HINDIM);
    mma_gemm<true,true,false><<<dim3(2, MT), 256, GEMM_SMEM>>>(buf0, Wt1, b_in1, buf1, N_NODES, HINDIM, HINDIM);
    mma_gemm<true,true,false><<<dim3(1, MT), 256, GEMM_SMEM>>>(buf1, Wt2, b_in2, H,    N_NODES, HINDIM, DDIM);

    const int mElems = N_NODES * K_REL * DDIM;
    const int scatterBlocks = (K_REL * E_EDGES * 32 + 255) / 256;

    for (int b = 0; b < 2; b++) {
        mma_gemm<false,false,false><<<dim3(1, MT), 256, GEMM_SMEM>>>(H, WmT + b * DDIM * DDIM, nullptr, Z, N_NODES, DDIM, DDIM);
        zero_kernel<<<4096, 256>>>(Mb, mElems);
        scatter_kernel<<<scatterBlocks, 256>>>(rows, cols, Z, Mb);
        mma_gemm<false,false,false><<<dim3(1, MT), 256, GEMM_SMEM>>>(H, Wg1hT + b * GATEH * DDIM, nullptr, gateH, N_NODES, DDIM, GATEH);
        mma_gemm<false,false,true><<<dim3(1, 625), 256, GEMM_SMEM>>>(Mb, Wg1mT + b * GATEH * DDIM, nullptr, G, N_NODES * K_REL, DDIM, GATEH);
        score_kernel<<<(N_NODES * K_REL * 32 + 255) / 256, 256>>>(G, gateH, logdeg, Wg1[b] + 2 * DDIM * GATEH,
                                                                  bg1[b], Wg2[b], bg2[b], scores);
        softmax_kernel<<<(N_NODES + 255) / 256, 256>>>(scores, mask, alpha + b * N_NODES * K_REL);
        zero_kernel<<<1, 256>>>(colsum, DDIM);
        zero_kernel<<<1, 32>>>(sumsq, 1);
        fused_kernel<<<N_NODES, DDIM>>>(Mb, alpha + b * N_NODES * K_REL, H, Xres, colsum, sumsq);
        stats_kernel<<<1, DDIM>>>(colsum, sumsq, stats);
        normalize_kernel<<<(N_NODES * DDIM + 255) / 256, 256>>>(Xres, stats, H);
    }

    mma_gemm<true,true,false><<<dim3(1, MT), 256, GEMM_SMEM>>>(H, Wh1T, bh1, hid, N_NODES, DDIM, DDIM);
    logits_kernel<<<(N_NODES * 32 + 255) / 256, 256>>>(hid, Wh2, bh2, out);
    copy_alpha_kernel<<<(2 * N_NODES * K_REL + 255) / 256, 256>>>(alpha, out, out_size);
}

// round 4
// speedup vs baseline: 1.5759x; 1.1315x over previous
#include <cuda_runtime.h>
#include <cuda_bf16.h>
#include <math.h>
#include <cstdint>

#define N_NODES 20000
#define K_REL   4
#define E_EDGES 320000
#define INDIM   1024
#define HINDIM  256
#define DDIM    128
#define GATEH   128
#define TEMP_INV (1.0f/0.6f)
#define MCLAMP  20.0f
#define NBUCKET (K_REL * N_NODES)

// ---------------- scratch (device globals; no allocation) ----------------
__device__ float g_buf0[N_NODES * HINDIM];
__device__ float g_buf1[N_NODES * HINDIM];
__device__ float g_H[N_NODES * DDIM];
__device__ float g_Z[N_NODES * DDIM];
__device__ float g_M[N_NODES * K_REL * DDIM];
__device__ float g_gateH[N_NODES * GATEH];
__device__ float g_G[N_NODES * K_REL * GATEH];
__device__ float g_scores[N_NODES * K_REL];
__device__ float g_alpha[2 * N_NODES * K_REL];
__device__ float g_Xres[N_NODES * DDIM];
__device__ float g_hid[N_NODES * DDIM];
__device__ float g_colsum[DDIM + 1];   // [128]=sumsq
__device__ float g_stats[DDIM + 1];
// CSR
__device__ int g_cnt[NBUCKET];
__device__ int g_off[NBUCKET + 1];
__device__ int g_cur[NBUCKET];
__device__ int g_ecol[K_REL * E_EDGES];
// transposed weights [N, K] K-major
__device__ float g_Wt0[HINDIM * INDIM];
__device__ float g_Wt1[HINDIM * HINDIM];
__device__ float g_Wt2[DDIM * HINDIM];
__device__ float g_WmT[2][DDIM * DDIM];
__device__ float g_Wg1hT[2][GATEH * DDIM];
__device__ float g_Wg1mT[2][GATEH * DDIM];
__device__ float g_Wh1T[DDIM * DDIM];

// ================= baseline-ISA tensor-core helpers =================
__device__ __forceinline__ uint32_t smem_u32(const void* p) {
    uint32_t a;
    asm("{ .reg .u64 t; cvta.to.shared.u64 t, %1; cvt.u32.u64 %0, t; }" : "=r"(a) : "l"(p));
    return a;
}
__device__ __forceinline__ void ldsm_x4(uint32_t* r, uint32_t addr) {
    asm volatile("ldmatrix.sync.aligned.m8n8.x4.shared.b16 {%0,%1,%2,%3}, [%4];"
        : "=r"(r[0]), "=r"(r[1]), "=r"(r[2]), "=r"(r[3]) : "r"(addr));
}
__device__ __forceinline__ void mma_bf16(float* c, const uint32_t* a, const uint32_t* b) {
    asm volatile("mma.sync.aligned.m16n8k16.row.col.f32.bf16.bf16.f32 "
        "{%0,%1,%2,%3}, {%4,%5,%6,%7}, {%8,%9}, {%0,%1,%2,%3};"
        : "+f"(c[0]), "+f"(c[1]), "+f"(c[2]), "+f"(c[3])
        : "r"(a[0]), "r"(a[1]), "r"(a[2]), "r"(a[3]), "r"(b[0]), "r"(b[1]));
}
__device__ __forceinline__ uint32_t pack_bf16(float a, float b) {
    __nv_bfloat162 h = __floats2bfloat162_rn(a, b);
    return *reinterpret_cast<uint32_t*>(&h);
}

// ================= bf16 3-split tensor-core GEMM =================
#define ROWB 80
#define TILE_B (128 * ROWB)
#define STAGE_B (4 * TILE_B)
#define GEMM_SMEM (2 * STAGE_B)

template <bool RELU, bool BIAS>
__global__ __launch_bounds__(256) void mma_gemm(
    const float* __restrict__ A, const float* __restrict__ Bt,
    const float* __restrict__ bias, float* __restrict__ C,
    int M, int K, int N)
{
    extern __shared__ __align__(128) char smem[];
    const int tid = threadIdx.x;
    const int lane = tid & 31;
    const int wid = tid >> 5;
    const int warp_m = wid & 3;
    const int warp_n = wid >> 2;
    const int rowBase = blockIdx.y * 128;
    const int colBase = blockIdx.x * 128;
    const int nch = K >> 5;

    float acc[2][8][4];
#pragma unroll
    for (int i = 0; i < 2; i++)
#pragma unroll
        for (int j = 0; j < 8; j++)
#pragma unroll
            for (int q = 0; q < 4; q++) acc[i][j][q] = 0.f;

    const uint32_t sb = smem_u32(smem);
    const int aRow = warp_m * 32 + (lane & 7) + ((lane >> 3) & 1) * 8;
    const int aK   = ((lane >> 4) & 1) * 8;
    const int bRow = warp_n * 64 + (lane & 7) + ((lane >> 4) & 1) * 8;
    const int bK   = ((lane >> 3) & 1) * 8;
    const uint32_t aBase = sb + (uint32_t)(aRow * ROWB + aK * 2);
    const uint32_t bBase = sb + 2u * TILE_B + (uint32_t)(bRow * ROWB + bK * 2);

    float4 aR[4], bR[4];

    auto gload = [&](int c) {
        const int k0 = c << 5;
#pragma unroll
        for (int j = 0; j < 4; j++) {
            int idx = tid + j * 256;
            int r = idx >> 3;
            int col = (idx & 7) * 4;
            int gr = rowBase + r;
            float4 v = make_float4(0.f, 0.f, 0.f, 0.f);
            if (gr < M) v = *reinterpret_cast<const float4*>(A + (size_t)gr * K + k0 + col);
            aR[j] = v;
            bR[j] = *reinterpret_cast<const float4*>(Bt + (size_t)(colBase + r) * K + k0 + col);
        }
    };
    auto sstore = [&](int s) {
        char* st = smem + s * STAGE_B;
#pragma unroll
        for (int j = 0; j < 4; j++) {
            int idx = tid + j * 256;
            int r = idx >> 3;
            int col = (idx & 7) * 4;
            int off = r * ROWB + col * 2;
            float4 v = aR[j];
            float hx = __bfloat162float(__float2bfloat16(v.x));
            float hy = __bfloat162float(__float2bfloat16(v.y));
            float hz = __bfloat162float(__float2bfloat16(v.z));
            float hw = __bfloat162float(__float2bfloat16(v.w));
            *reinterpret_cast<uint2*>(st + off) =
                make_uint2(pack_bf16(hx, hy), pack_bf16(hz, hw));
            *reinterpret_cast<uint2*>(st + TILE_B + off) =
                make_uint2(pack_bf16(v.x - hx, v.y - hy), pack_bf16(v.z - hz, v.w - hw));
            float4 w = bR[j];
            float gx = __bfloat162float(__float2bfloat16(w.x));
            float gy = __bfloat162float(__float2bfloat16(w.y));
            float gz = __bfloat162float(__float2bfloat16(w.z));
            float gw = __bfloat162float(__float2bfloat16(w.w));
            *reinterpret_cast<uint2*>(st + 2 * TILE_B + off) =
                make_uint2(pack_bf16(gx, gy), pack_bf16(gz, gw));
            *reinterpret_cast<uint2*>(st + 3 * TILE_B + off) =
                make_uint2(pack_bf16(w.x - gx, w.y - gy), pack_bf16(w.z - gz, w.w - gw));
        }
    };

    gload(0);
    sstore(0);
    __syncthreads();

    for (int c = 0; c < nch; c++) {
        const int s = c & 1;
        const uint32_t stoff = (uint32_t)s * STAGE_B;
        if (c + 1 < nch) gload(c + 1);

#pragma unroll
        for (int ks = 0; ks < 2; ks++) {
            uint32_t ah[2][4], al[2][4], bh[4][4], bl[4][4];
#pragma unroll
            for (int mt = 0; mt < 2; mt++) {
                ldsm_x4(ah[mt], aBase + stoff + mt * 16 * ROWB + ks * 32);
                ldsm_x4(al[mt], aBase + stoff + TILE_B + mt * 16 * ROWB + ks * 32);
            }
#pragma unroll
            for (int p = 0; p < 4; p++) {
                ldsm_x4(bh[p], bBase + stoff + p * 16 * ROWB + ks * 32);
                ldsm_x4(bl[p], bBase + stoff + TILE_B + p * 16 * ROWB + ks * 32);
            }
#pragma unroll
            for (int mt = 0; mt < 2; mt++) {
#pragma unroll
                for (int nt = 0; nt < 8; nt++) {
                    const uint32_t* bhp = &bh[nt >> 1][(nt & 1) * 2];
                    const uint32_t* blp = &bl[nt >> 1][(nt & 1) * 2];
                    mma_bf16(acc[mt][nt], ah[mt], bhp);
                    mma_bf16(acc[mt][nt], ah[mt], blp);
                    mma_bf16(acc[mt][nt], al[mt], bhp);
                }
            }
        }
        if (c + 1 < nch) sstore((c + 1) & 1);
        __syncthreads();
    }

    const int g = lane >> 2;
    const int tc2 = (lane & 3) * 2;
#pragma unroll
    for (int mt = 0; mt < 2; mt++) {
#pragma unroll
        for (int nt = 0; nt < 8; nt++) {
            int row0 = rowBase + warp_m * 32 + mt * 16 + g;
            int col = colBase + warp_n * 64 + nt * 8 + tc2;
            float c0 = acc[mt][nt][0], c1 = acc[mt][nt][1];
            float c2 = acc[mt][nt][2], c3 = acc[mt][nt][3];
            if (BIAS) {
                float2 bb = *reinterpret_cast<const float2*>(bias + col);
                c0 += bb.x; c1 += bb.y; c2 += bb.x; c3 += bb.y;
            }
            if (RELU) {
                c0 = fmaxf(c0, 0.f); c1 = fmaxf(c1, 0.f);
                c2 = fmaxf(c2, 0.f); c3 = fmaxf(c3, 0.f);
            }
            if (row0 < M)
                *reinterpret_cast<float2*>(C + (size_t)row0 * N + col) = make_float2(c0, c1);
            if (row0 + 8 < M)
                *reinterpret_cast<float2*>(C + (size_t)(row0 + 8) * N + col) = make_float2(c2, c3);
        }
    }
}

// ================= batched transpose (one launch for all weights) =================
struct TJob { const float* src; float* dst; int K; int N; };
struct TJobs { TJob j[10]; };

__global__ void transpose_multi(TJobs jobs)
{
    __shared__ float t[32][33];
    TJob jb = jobs.j[blockIdx.z];
    int k0 = blockIdx.y * 32, n0 = blockIdx.x * 32;
    if (k0 >= jb.K || n0 >= jb.N) return;
    int tx = threadIdx.x, ty = threadIdx.y;
    for (int i = ty; i < 32; i += 8) {
        int k = k0 + i, n = n0 + tx;
        t[i][tx] = (k < jb.K && n < jb.N) ? jb.src[(size_t)k * jb.N + n] : 0.f;
    }
    __syncthreads();
    for (int i = ty; i < 32; i += 8) {
        int n = n0 + i, k = k0 + tx;
        if (n < jb.N && k < jb.K) jb.dst[(size_t)n * jb.K + k] = t[tx][i];
    }
}

// ================= CSR build =================
__global__ void zero_int_kernel(int* p, int n) {
    int i = blockIdx.x * blockDim.x + threadIdx.x;
    if (i < n) p[i] = 0;
}
__global__ void hist_kernel(const int* __restrict__ rows, int* __restrict__ cnt) {
    int i = blockIdx.x * blockDim.x + threadIdx.x;
    if (i >= K_REL * E_EDGES) return;
    int k = i / E_EDGES;
    atomicAdd(&cnt[k * N_NODES + rows[i]], 1);
}
#define SCAN_T 1024
#define SCAN_CHUNK ((NBUCKET + SCAN_T - 1) / SCAN_T)
__global__ __launch_bounds__(SCAN_T) void scan_kernel(const int* __restrict__ cnt,
                                                      int* __restrict__ off, int* __restrict__ cur)
{
    int t = threadIdx.x;
    int start = t * SCAN_CHUNK;
    int end = start + SCAN_CHUNK; if (end > NBUCKET) end = NBUCKET;
    int local = 0;
    for (int i = start; i < end; i++) local += cnt[i];
    __shared__ int ss[SCAN_T];
    ss[t] = local; __syncthreads();
    for (int d = 1; d < SCAN_T; d <<= 1) {
        int v = (t >= d) ? ss[t - d] : 0;
        __syncthreads();
        ss[t] += v;
        __syncthreads();
    }
    int run = ss[t] - local;
    for (int i = start; i < end; i++) {
        off[i] = run; cur[i] = run; run += cnt[i];
    }
    if (t == SCAN_T - 1) off[NBUCKET] = ss[SCAN_T - 1];
}
__global__ void fill_kernel(const int* __restrict__ rows, const int* __restrict__ cols,
                            int* __restrict__ cur, int* __restrict__ ecol)
{
    int i = blockIdx.x * blockDim.x + threadIdx.x;
    if (i >= K_REL * E_EDGES) return;
    int k = i / E_EDGES;
    int p = atomicAdd(&cur[k * N_NODES + rows[i]], 1);
    ecol[p] = cols[i];
}

// ================= gather: M[n,k,:] = clip(sum_{e in bucket} Z[col_e,:]) =================
__global__ void gather_kernel(const int* __restrict__ off, const int* __restrict__ ecol,
                              const float* __restrict__ Z, float* __restrict__ Mb)
{
    int w = (blockIdx.x * blockDim.x + threadIdx.x) >> 5;
    int lane = threadIdx.x & 31;
    if (w >= NBUCKET) return;
    int k = w / N_NODES;
    int n = w - k * N_NODES;
    int s = off[w], t = off[w + 1];
    float4 a0 = make_float4(0.f, 0.f, 0.f, 0.f);
    float4 a1 = make_float4(0.f, 0.f, 0.f, 0.f);
    int e = s;
    for (; e + 2 <= t; e += 2) {
        int c0 = ecol[e], c1 = ecol[e + 1];
        float4 v0 = reinterpret_cast<const float4*>(Z + (size_t)c0 * DDIM)[lane];
        float4 v1 = reinterpret_cast<const float4*>(Z + (size_t)c1 * DDIM)[lane];
        a0.x += v0.x; a0.y += v0.y; a0.z += v0.z; a0.w += v0.w;
        a1.x += v1.x; a1.y += v1.y; a1.z += v1.z; a1.w += v1.w;
    }
    if (e < t) {
        int c0 = ecol[e];
        float4 v0 = reinterpret_cast<const float4*>(Z + (size_t)c0 * DDIM)[lane];
        a0.x += v0.x; a0.y += v0.y; a0.z += v0.z; a0.w += v0.w;
    }
    float4 r;
    r.x = fminf(fmaxf(a0.x + a1.x, -MCLAMP), MCLAMP);
    r.y = fminf(fmaxf(a0.y + a1.y, -MCLAMP), MCLAMP);
    r.z = fminf(fmaxf(a0.z + a1.z, -MCLAMP), MCLAMP);
    r.w = fminf(fmaxf(a0.w + a1.w, -MCLAMP), MCLAMP);
    reinterpret_cast<float4*>(Mb + ((size_t)n * K_REL + k) * DDIM)[lane] = r;
}

// ================= misc kernels =================
__global__ void zero_kernel(float* p, int n) {
    int i = blockIdx.x * blockDim.x + threadIdx.x;
    if (i < n) p[i] = 0.f;
}

__global__ void score_kernel(const float* __restrict__ G, const float* __restrict__ gateH,
                             const float* __restrict__ logdeg, const float* __restrict__ w_ld,
                             const float* __restrict__ bg1, const float* __restrict__ Wg2,
                             const float* __restrict__ bg2, float* __restrict__ scores)
{
    int warp = (blockIdx.x * blockDim.x + threadIdx.x) >> 5;
    int lane = threadIdx.x & 31;
    if (warp >= N_NODES * K_REL) return;
    int n = warp >> 2;
    float ld = logdeg[warp];
    float acc = 0.f;
#pragma unroll
    for (int i = 0; i < 4; i++) {
        int d = lane + i * 32;
        float v = G[(long long)warp * GATEH + d] + gateH[(long long)n * GATEH + d]
                + ld * w_ld[d] + bg1[d];
        v = fmaxf(v, 0.f);
        acc += v * Wg2[d];
    }
#pragma unroll
    for (int o = 16; o > 0; o >>= 1) acc += __shfl_xor_sync(0xFFFFFFFFu, acc, o);
    if (lane == 0) scores[warp] = acc + bg2[0];
}

__global__ void softmax_kernel(const float* __restrict__ scores, const float* __restrict__ mask,
                               float* __restrict__ alpha)
{
    int n = blockIdx.x * blockDim.x + threadIdx.x;
    if (n >= N_NODES) return;
    float s[K_REL], a[K_REL];
    float m = -1e30f;
#pragma unroll
    for (int k = 0; k < K_REL; k++) { s[k] = scores[n * K_REL + k] * TEMP_INV; m = fmaxf(m, s[k]); }
    float sum = 0.f;
#pragma unroll
    for (int k = 0; k < K_REL; k++) { a[k] = __expf(s[k] - m); sum += a[k]; }
    float inv = 1.f / sum;
    float sum2 = 0.f;
#pragma unroll
    for (int k = 0; k < K_REL; k++) { a[k] = a[k] * inv * mask[n * K_REL + k]; sum2 += a[k]; }
    float inv2 = 1.f / fmaxf(sum2, 1e-12f);
    float sum3 = 0.f;
#pragma unroll
    for (int k = 0; k < K_REL; k++) { a[k] = fmaxf(a[k] * inv2, 1e-8f); sum3 += a[k]; }
    float inv3 = 1.f / fmaxf(sum3, 1e-12f);
#pragma unroll
    for (int k = 0; k < K_REL; k++) alpha[n * K_REL + k] = a[k] * inv3;
}

__global__ void fused_kernel(const float* __restrict__ Mb, const float* __restrict__ alpha,
                             const float* __restrict__ H, float* __restrict__ Xres,
                             float* __restrict__ colsum)
{
    int n = blockIdx.x;
    int d = threadIdx.x;
    __shared__ float a[K_REL];
    __shared__ float wsum[4];
    if (d < K_REL) a[d] = alpha[n * K_REL + d];
    __syncthreads();
    float f = 0.f;
#pragma unroll
    for (int k = 0; k < K_REL; k++)
        f += a[k] * Mb[((long long)n * K_REL + k) * DDIM + d];
    float x = f + H[(long long)n * DDIM + d];
    Xres[(long long)n * DDIM + d] = x;
    atomicAdd(&colsum[d], x);
    float q = x * x;
#pragma unroll
    for (int o = 16; o > 0; o >>= 1) q += __shfl_xor_sync(0xFFFFFFFFu, q, o);
    if ((d & 31) == 0) wsum[d >> 5] = q;
    __syncthreads();
    if (d == 0) atomicAdd(&colsum[DDIM], wsum[0] + wsum[1] + wsum[2] + wsum[3]);
}

__global__ void stats_kernel(const float* __restrict__ colsum, float* __restrict__ stats)
{
    int d = threadIdx.x;
    __shared__ float wsum[4];
    float mu = colsum[d] * (1.0f / N_NODES);
    stats[d] = mu;
    float q = mu * mu;
#pragma unroll
    for (int o = 16; o > 0; o >>= 1) q += __shfl_xor_sync(0xFFFFFFFFu, q, o);
    if ((d & 31) == 0) wsum[d >> 5] = q;
    __syncthreads();
    if (d == 0) {
        float summu2 = wsum[0] + wsum[1] + wsum[2] + wsum[3];
        float var = (colsum[DDIM] - (float)N_NODES * summu2) * (1.0f / N_NODES);
        var = fmaxf(var, 0.f);
        stats[DDIM] = 1.0f / (sqrtf(var) + 1e-6f);
    }
}

__global__ void normalize_kernel(const float* __restrict__ Xres, const float* __restrict__ stats,
                                 float* __restrict__ H)
{
    int i = blockIdx.x * blockDim.x + threadIdx.x;
    if (i >= N_NODES * DDIM) return;
    int d = i & (DDIM - 1);
    float v = (Xres[i] - stats[d]) * stats[DDIM];
    H[i] = fmaxf(v, 0.f);
}

__global__ void logits_kernel(const float* __restrict__ hid, const float* __restrict__ Wh2,
                              const float* __restrict__ bh2, float* __restrict__ out)
{
    int warp = (blockIdx.x * blockDim.x + threadIdx.x) >> 5;
    int lane = threadIdx.x & 31;
    if (warp >= N_NODES) return;
    float acc = 0.f;
#pragma unroll
    for (int i = 0; i < 4; i++) {
        int d = lane + i * 32;
        acc += hid[(long long)warp * DDIM + d] * Wh2[d];
    }
#pragma unroll
    for (int o = 16; o > 0; o >>= 1) acc += __shfl_xor_sync(0xFFFFFFFFu, acc, o);
    if (lane == 0) out[warp] = acc + bh2[0];
}

__global__ void copy_alpha_kernel(const float* __restrict__ alpha, float* __restrict__ out,
                                  int out_size)
{
    int i = blockIdx.x * blockDim.x + threadIdx.x;
    if (i >= 2 * N_NODES * K_REL) return;
    if (N_NODES + i < out_size) out[N_NODES + i] = alpha[i];
}

// ================= host =================
extern "C" void kernel_launch(void* const* d_in, const int* in_sizes, int n_in,
                              void* d_out, int out_size)
{
    const float* X      = (const float*)d_in[0];
    const int*   rows   = (const int*)d_in[1];
    const int*   cols   = (const int*)d_in[2];
    const float* mask   = (const float*)d_in[3];
    const float* logdeg = (const float*)d_in[4];
    const float* W_in0  = (const float*)d_in[5];
    const float* b_in0  = (const float*)d_in[6];
    const float* W_in1  = (const float*)d_in[7];
    const float* b_in1  = (const float*)d_in[8];
    const float* W_in2  = (const float*)d_in[9];
    const float* b_in2  = (const float*)d_in[10];
    const float* Wmsg[2]  = {(const float*)d_in[11], (const float*)d_in[16]};
    const float* Wg1[2]   = {(const float*)d_in[12], (const float*)d_in[17]};
    const float* bg1[2]   = {(const float*)d_in[13], (const float*)d_in[18]};
    const float* Wg2[2]   = {(const float*)d_in[14], (const float*)d_in[19]};
    const float* bg2[2]   = {(const float*)d_in[15], (const float*)d_in[20]};
    const float* Wh1    = (const float*)d_in[21];
    const float* bh1    = (const float*)d_in[22];
    const float* Wh2    = (const float*)d_in[23];
    const float* bh2    = (const float*)d_in[24];
    float* out = (float*)d_out;

    float *buf0, *buf1, *H, *Z, *Mb, *gateH, *G, *scores, *alpha, *Xres, *hid, *colsum, *stats;
    float *Wt0, *Wt1, *Wt2, *WmT, *Wg1hT, *Wg1mT, *Wh1T;
    int *cnt, *off, *cur, *ecol;
    cudaGetSymbolAddress((void**)&buf0,  g_buf0);
    cudaGetSymbolAddress((void**)&buf1,  g_buf1);
    cudaGetSymbolAddress((void**)&H,     g_H);
    cudaGetSymbolAddress((void**)&Z,     g_Z);
    cudaGetSymbolAddress((void**)&Mb,    g_M);
    cudaGetSymbolAddress((void**)&gateH, g_gateH);
    cudaGetSymbolAddress((void**)&G,     g_G);
    cudaGetSymbolAddress((void**)&scores,g_scores);
    cudaGetSymbolAddress((void**)&alpha, g_alpha);
    cudaGetSymbolAddress((void**)&Xres,  g_Xres);
    cudaGetSymbolAddress((void**)&hid,   g_hid);
    cudaGetSymbolAddress((void**)&colsum,g_colsum);
    cudaGetSymbolAddress((void**)&stats, g_stats);
    cudaGetSymbolAddress((void**)&cnt,   g_cnt);
    cudaGetSymbolAddress((void**)&off,   g_off);
    cudaGetSymbolAddress((void**)&cur,   g_cur);
    cudaGetSymbolAddress((void**)&ecol,  g_ecol);
    cudaGetSymbolAddress((void**)&Wt0,   g_Wt0);
    cudaGetSymbolAddress((void**)&Wt1,   g_Wt1);
    cudaGetSymbolAddress((void**)&Wt2,   g_Wt2);
    cudaGetSymbolAddress((void**)&WmT,   g_WmT);
    cudaGetSymbolAddress((void**)&Wg1hT, g_Wg1hT);
    cudaGetSymbolAddress((void**)&Wg1mT, g_Wg1mT);
    cudaGetSymbolAddress((void**)&Wh1T,  g_Wh1T);

    cudaFuncSetAttribute(mma_gemm<true,true>,   cudaFuncAttributeMaxDynamicSharedMemorySize, GEMM_SMEM);
    cudaFuncSetAttribute(mma_gemm<false,false>, cudaFuncAttributeMaxDynamicSharedMemorySize, GEMM_SMEM);

    // launch 0: all weight transposes in one batched kernel
    TJobs jobs;
    jobs.j[0] = { W_in0, Wt0, INDIM, HINDIM };
    jobs.j[1] = { W_in1, Wt1, HINDIM, HINDIM };
    jobs.j[2] = { W_in2, Wt2, HINDIM, DDIM };
    jobs.j[3] = { Wmsg[0], WmT,                      DDIM, DDIM };
    jobs.j[4] = { Wg1[0],  Wg1hT,                    DDIM, GATEH };
    jobs.j[5] = { Wg1[0] + DDIM * GATEH, Wg1mT,      DDIM, GATEH };
    jobs.j[6] = { Wmsg[1], WmT + DDIM * DDIM,        DDIM, DDIM };
    jobs.j[7] = { Wg1[1],  Wg1hT + GATEH * DDIM,     DDIM, GATEH };
    jobs.j[8] = { Wg1[1] + DDIM * GATEH, Wg1mT + GATEH * DDIM, DDIM, GATEH };
    jobs.j[9] = { Wh1, Wh1T, DDIM, DDIM };
    transpose_multi<<<dim3(8, 32, 10), dim3(32, 8)>>>(jobs);

    // launches 1-4: CSR build (independent of GEMMs)
    zero_int_kernel<<<(NBUCKET + 255) / 256, 256>>>(cnt, NBUCKET);
    hist_kernel<<<(K_REL * E_EDGES + 255) / 256, 256>>>(rows, cnt);
    scan_kernel<<<1, SCAN_T>>>(cnt, off, cur);
    fill_kernel<<<(K_REL * E_EDGES + 255) / 256, 256>>>(rows, cols, cur, ecol);

    const int MT = (N_NODES + 127) / 128;  // 157

    // launch 5 (profiled): encoder GEMM 1
    mma_gemm<true,true><<<dim3(2, MT), 256, GEMM_SMEM>>>(X,    Wt0, b_in0, buf0, N_NODES, INDIM,  HINDIM);
    mma_gemm<true,true><<<dim3(2, MT), 256, GEMM_SMEM>>>(buf0, Wt1, b_in1, buf1, N_NODES, HINDIM, HINDIM);
    mma_gemm<true,true><<<dim3(1, MT), 256, GEMM_SMEM>>>(buf1, Wt2, b_in2, H,    N_NODES, HINDIM, DDIM);

    for (int b = 0; b < 2; b++) {
        mma_gemm<false,false><<<dim3(1, MT), 256, GEMM_SMEM>>>(H, WmT + b * DDIM * DDIM, nullptr, Z, N_NODES, DDIM, DDIM);
        gather_kernel<<<(NBUCKET * 32 + 255) / 256, 256>>>(off, ecol, Z, Mb);
        mma_gemm<false,false><<<dim3(1, MT), 256, GEMM_SMEM>>>(H, Wg1hT + b * GATEH * DDIM, nullptr, gateH, N_NODES, DDIM, GATEH);
        mma_gemm<false,false><<<dim3(1, 625), 256, GEMM_SMEM>>>(Mb, Wg1mT + b * GATEH * DDIM, nullptr, G, N_NODES * K_REL, DDIM, GATEH);
        score_kernel<<<(N_NODES * K_REL * 32 + 255) / 256, 256>>>(G, gateH, logdeg, Wg1[b] + 2 * DDIM * GATEH,
                                                                  bg1[b], Wg2[b], bg2[b], scores);
        softmax_kernel<<<(N_NODES + 255) / 256, 256>>>(scores, mask, alpha + b * N_NODES * K_REL);
        zero_kernel<<<1, 256>>>(colsum, DDIM + 1);
        fused_kernel<<<N_NODES, DDIM>>>(Mb, alpha + b * N_NODES * K_REL, H, Xres, colsum);
        stats_kernel<<<1, DDIM>>>(colsum, stats);
        normalize_kernel<<<(N_NODES * DDIM + 255) / 256, 256>>>(Xres, stats, H);
    }

    mma_gemm<true,true><<<dim3(1, MT), 256, GEMM_SMEM>>>(H, Wh1T, bh1, hid, N_NODES, DDIM, DDIM);
    logits_kernel<<<(N_NODES * 32 + 255) / 256, 256>>>(hid, Wh2, bh2, out);
    copy_alpha_kernel<<<(2 * N_NODES * K_REL + 255) / 256, 256>>>(alpha, out, out_size);
}

// round 5
// speedup vs baseline: 2.2398x; 1.4213x over previous
#include <cuda_runtime.h>
#include <cuda_bf16.h>
#include <math.h>
#include <cstdint>

#define N_NODES 20000
#define K_REL   4
#define E_EDGES 320000
#define INDIM   1024
#define HINDIM  256
#define DDIM    128
#define GATEH   128
#define TEMP_INV (1.0f/0.6f)
#define MCLAMP  20.0f
#define NBUCKET (K_REL * N_NODES)

// ---------------- scratch (device globals; no allocation) ----------------
__device__ float g_buf0[N_NODES * HINDIM];
__device__ float g_buf1[N_NODES * HINDIM];
__device__ float g_H[N_NODES * DDIM];
__device__ float g_Z[N_NODES * DDIM];
__device__ float g_M[N_NODES * K_REL * DDIM];
__device__ float g_gateH[N_NODES * GATEH];
__device__ float g_G[N_NODES * K_REL * GATEH];
__device__ float g_scores[N_NODES * K_REL];
__device__ float g_alpha[2 * N_NODES * K_REL];
__device__ float g_Xres[N_NODES * DDIM];
__device__ float g_hid[N_NODES * DDIM];
__device__ float g_colsum[DDIM + 1];   // [128]=sumsq
__device__ float g_stats[DDIM + 1];
// CSR
__device__ int g_cnt[NBUCKET];
__device__ int g_off[NBUCKET + 1];
__device__ int g_cur[NBUCKET];
__device__ int g_ecol[K_REL * E_EDGES];
__device__ int g_bsum[256];
__device__ int g_btop[256];
// transposed weights [N, K] K-major
__device__ float g_Wt0[HINDIM * INDIM];
__device__ float g_Wt1[HINDIM * HINDIM];
__device__ float g_Wt2[DDIM * HINDIM];
__device__ float g_WmT[2][DDIM * DDIM];
__device__ float g_Wg1hT[2][GATEH * DDIM];
__device__ float g_Wg1mT[2][GATEH * DDIM];
__device__ float g_Wh1T[DDIM * DDIM];

// ================= baseline-ISA tensor-core helpers =================
__device__ __forceinline__ uint32_t smem_u32(const void* p) {
    uint32_t a;
    asm("{ .reg .u64 t; cvta.to.shared.u64 t, %1; cvt.u32.u64 %0, t; }" : "=r"(a) : "l"(p));
    return a;
}
__device__ __forceinline__ void ldsm_x4(uint32_t* r, uint32_t addr) {
    asm volatile("ldmatrix.sync.aligned.m8n8.x4.shared.b16 {%0,%1,%2,%3}, [%4];"
        : "=r"(r[0]), "=r"(r[1]), "=r"(r[2]), "=r"(r[3]) : "r"(addr));
}
__device__ __forceinline__ void mma_bf16(float* c, const uint32_t* a, const uint32_t* b) {
    asm volatile("mma.sync.aligned.m16n8k16.row.col.f32.bf16.bf16.f32 "
        "{%0,%1,%2,%3}, {%4,%5,%6,%7}, {%8,%9}, {%0,%1,%2,%3};"
        : "+f"(c[0]), "+f"(c[1]), "+f"(c[2]), "+f"(c[3])
        : "r"(a[0]), "r"(a[1]), "r"(a[2]), "r"(a[3]), "r"(b[0]), "r"(b[1]));
}
__device__ __forceinline__ uint32_t pack_bf16(float a, float b) {
    __nv_bfloat162 h = __floats2bfloat162_rn(a, b);
    return *reinterpret_cast<uint32_t*>(&h);
}

// ================= bf16 3-split tensor-core GEMM =================
#define ROWB 80
#define TILE_B (128 * ROWB)
#define STAGE_B (4 * TILE_B)
#define GEMM_SMEM (2 * STAGE_B)

template <bool RELU, bool BIAS>
__global__ __launch_bounds__(256) void mma_gemm(
    const float* __restrict__ A, const float* __restrict__ Bt,
    const float* __restrict__ bias, float* __restrict__ C,
    int M, int K, int N)
{
    extern __shared__ __align__(128) char smem[];
    const int tid = threadIdx.x;
    const int lane = tid & 31;
    const int wid = tid >> 5;
    const int warp_m = wid & 3;
    const int warp_n = wid >> 2;
    const int rowBase = blockIdx.y * 128;
    const int colBase = blockIdx.x * 128;
    const int nch = K >> 5;

    float acc[2][8][4];
#pragma unroll
    for (int i = 0; i < 2; i++)
#pragma unroll
        for (int j = 0; j < 8; j++)
#pragma unroll
            for (int q = 0; q < 4; q++) acc[i][j][q] = 0.f;

    const uint32_t sb = smem_u32(smem);
    const int aRow = warp_m * 32 + (lane & 7) + ((lane >> 3) & 1) * 8;
    const int aK   = ((lane >> 4) & 1) * 8;
    const int bRow = warp_n * 64 + (lane & 7) + ((lane >> 4) & 1) * 8;
    const int bK   = ((lane >> 3) & 1) * 8;
    const uint32_t aBase = sb + (uint32_t)(aRow * ROWB + aK * 2);
    const uint32_t bBase = sb + 2u * TILE_B + (uint32_t)(bRow * ROWB + bK * 2);

    float4 aR[4], bR[4];

    auto gload = [&](int c) {
        const int k0 = c << 5;
#pragma unroll
        for (int j = 0; j < 4; j++) {
            int idx = tid + j * 256;
            int r = idx >> 3;
            int col = (idx & 7) * 4;
            int gr = rowBase + r;
            float4 v = make_float4(0.f, 0.f, 0.f, 0.f);
            if (gr < M) v = *reinterpret_cast<const float4*>(A + (size_t)gr * K + k0 + col);
            aR[j] = v;
            bR[j] = *reinterpret_cast<const float4*>(Bt + (size_t)(colBase + r) * K + k0 + col);
        }
    };
    auto sstore = [&](int s) {
        char* st = smem + s * STAGE_B;
#pragma unroll
        for (int j = 0; j < 4; j++) {
            int idx = tid + j * 256;
            int r = idx >> 3;
            int col = (idx & 7) * 4;
            int off = r * ROWB + col * 2;
            float4 v = aR[j];
            float hx = __bfloat162float(__float2bfloat16(v.x));
            float hy = __bfloat162float(__float2bfloat16(v.y));
            float hz = __bfloat162float(__float2bfloat16(v.z));
            float hw = __bfloat162float(__float2bfloat16(v.w));
            *reinterpret_cast<uint2*>(st + off) =
                make_uint2(pack_bf16(hx, hy), pack_bf16(hz, hw));
            *reinterpret_cast<uint2*>(st + TILE_B + off) =
                make_uint2(pack_bf16(v.x - hx, v.y - hy), pack_bf16(v.z - hz, v.w - hw));
            float4 w = bR[j];
            float gx = __bfloat162float(__float2bfloat16(w.x));
            float gy = __bfloat162float(__float2bfloat16(w.y));
            float gz = __bfloat162float(__float2bfloat16(w.z));
            float gw = __bfloat162float(__float2bfloat16(w.w));
            *reinterpret_cast<uint2*>(st + 2 * TILE_B + off) =
                make_uint2(pack_bf16(gx, gy), pack_bf16(gz, gw));
            *reinterpret_cast<uint2*>(st + 3 * TILE_B + off) =
                make_uint2(pack_bf16(w.x - gx, w.y - gy), pack_bf16(w.z - gz, w.w - gw));
        }
    };

    gload(0);
    sstore(0);
    __syncthreads();

    for (int c = 0; c < nch; c++) {
        const int s = c & 1;
        const uint32_t stoff = (uint32_t)s * STAGE_B;
        if (c + 1 < nch) gload(c + 1);

#pragma unroll
        for (int ks = 0; ks < 2; ks++) {
            uint32_t ah[2][4], al[2][4], bh[4][4], bl[4][4];
#pragma unroll
            for (int mt = 0; mt < 2; mt++) {
                ldsm_x4(ah[mt], aBase + stoff + mt * 16 * ROWB + ks * 32);
                ldsm_x4(al[mt], aBase + stoff + TILE_B + mt * 16 * ROWB + ks * 32);
            }
#pragma unroll
            for (int p = 0; p < 4; p++) {
                ldsm_x4(bh[p], bBase + stoff + p * 16 * ROWB + ks * 32);
                ldsm_x4(bl[p], bBase + stoff + TILE_B + p * 16 * ROWB + ks * 32);
            }
#pragma unroll
            for (int mt = 0; mt < 2; mt++) {
#pragma unroll
                for (int nt = 0; nt < 8; nt++) {
                    const uint32_t* bhp = &bh[nt >> 1][(nt & 1) * 2];
                    const uint32_t* blp = &bl[nt >> 1][(nt & 1) * 2];
                    mma_bf16(acc[mt][nt], ah[mt], bhp);
                    mma_bf16(acc[mt][nt], ah[mt], blp);
                    mma_bf16(acc[mt][nt], al[mt], bhp);
                }
            }
        }
        if (c + 1 < nch) sstore((c + 1) & 1);
        __syncthreads();
    }

    const int g = lane >> 2;
    const int tc2 = (lane & 3) * 2;
#pragma unroll
    for (int mt = 0; mt < 2; mt++) {
#pragma unroll
        for (int nt = 0; nt < 8; nt++) {
            int row0 = rowBase + warp_m * 32 + mt * 16 + g;
            int col = colBase + warp_n * 64 + nt * 8 + tc2;
            float c0 = acc[mt][nt][0], c1 = acc[mt][nt][1];
            float c2 = acc[mt][nt][2], c3 = acc[mt][nt][3];
            if (BIAS) {
                float2 bb = *reinterpret_cast<const float2*>(bias + col);
                c0 += bb.x; c1 += bb.y; c2 += bb.x; c3 += bb.y;
            }
            if (RELU) {
                c0 = fmaxf(c0, 0.f); c1 = fmaxf(c1, 0.f);
                c2 = fmaxf(c2, 0.f); c3 = fmaxf(c3, 0.f);
            }
            if (row0 < M)
                *reinterpret_cast<float2*>(C + (size_t)row0 * N + col) = make_float2(c0, c1);
            if (row0 + 8 < M)
                *reinterpret_cast<float2*>(C + (size_t)(row0 + 8) * N + col) = make_float2(c2, c3);
        }
    }
}

// ================= batched transpose =================
struct TJob { const float* src; float* dst; int K; int N; };
struct TJobs { TJob j[10]; };

__global__ void transpose_multi(TJobs jobs)
{
    __shared__ float t[32][33];
    TJob jb = jobs.j[blockIdx.z];
    int k0 = blockIdx.y * 32, n0 = blockIdx.x * 32;
    if (k0 >= jb.K || n0 >= jb.N) return;
    int tx = threadIdx.x, ty = threadIdx.y;
    for (int i = ty; i < 32; i += 8) {
        int k = k0 + i, n = n0 + tx;
        t[i][tx] = (k < jb.K && n < jb.N) ? jb.src[(size_t)k * jb.N + n] : 0.f;
    }
    __syncthreads();
    for (int i = ty; i < 32; i += 8) {
        int n = n0 + i, k = k0 + tx;
        if (n < jb.N && k < jb.K) jb.dst[(size_t)n * jb.K + k] = t[tx][i];
    }
}

// ================= CSR build (multi-block scan) =================
#define SCB 160           // scan blocks
#define SCT 256           // threads per scan block
#define SPT 2             // buckets per thread (160*256*2 = 81920 >= 80000)

__global__ void zero_int_kernel(int* p, int n) {
    int i = blockIdx.x * blockDim.x + threadIdx.x;
    if (i < n) p[i] = 0;
}
__global__ void hist_kernel(const int* __restrict__ rows, int* __restrict__ cnt) {
    int i = blockIdx.x * blockDim.x + threadIdx.x;
    if (i >= K_REL * E_EDGES) return;
    int k = i / E_EDGES;
    atomicAdd(&cnt[k * N_NODES + rows[i]], 1);
}
// phase A: per-block bucket sums
__global__ __launch_bounds__(SCT) void scan_part(const int* __restrict__ cnt, int* __restrict__ bsum)
{
    __shared__ int ss[SCT];
    int b = blockIdx.x, t = threadIdx.x;
    int base = b * SCT * SPT + t * SPT;
    int local = 0;
#pragma unroll
    for (int i = 0; i < SPT; i++) {
        int idx = base + i;
        if (idx < NBUCKET) local += cnt[idx];
    }
    ss[t] = local; __syncthreads();
    for (int d = SCT >> 1; d > 0; d >>= 1) {
        if (t < d) ss[t] += ss[t + d];
        __syncthreads();
    }
    if (t == 0) bsum[b] = ss[0];
}
// phase B: scan block partials (tiny)
__global__ __launch_bounds__(SCT) void scan_top(const int* __restrict__ bsum,
                                                int* __restrict__ btop, int* __restrict__ off)
{
    __shared__ int ss[SCT];
    int t = threadIdx.x;
    int v = (t < SCB) ? bsum[t] : 0;
    ss[t] = v; __syncthreads();
    for (int d = 1; d < SCT; d <<= 1) {
        int u = (t >= d) ? ss[t - d] : 0;
        __syncthreads();
        ss[t] += u;
        __syncthreads();
    }
    if (t < SCB) btop[t] = ss[t] - v;       // exclusive prefix
    if (t == SCB - 1) off[NBUCKET] = ss[t]; // total
}
// phase C: per-block interior scan, write off/cur
__global__ __launch_bounds__(SCT) void scan_write(const int* __restrict__ cnt,
                                                  const int* __restrict__ btop,
                                                  int* __restrict__ off, int* __restrict__ cur)
{
    __shared__ int ss[SCT];
    int b = blockIdx.x, t = threadIdx.x;
    int base = b * SCT * SPT + t * SPT;
    int c[SPT];
    int local = 0;
#pragma unroll
    for (int i = 0; i < SPT; i++) {
        int idx = base + i;
        c[i] = (idx < NBUCKET) ? cnt[idx] : 0;
        local += c[i];
    }
    ss[t] = local; __syncthreads();
    for (int d = 1; d < SCT; d <<= 1) {
        int u = (t >= d) ? ss[t - d] : 0;
        __syncthreads();
        ss[t] += u;
        __syncthreads();
    }
    int run = btop[b] + ss[t] - local;
#pragma unroll
    for (int i = 0; i < SPT; i++) {
        int idx = base + i;
        if (idx < NBUCKET) { off[idx] = run; cur[idx] = run; run += c[i]; }
    }
}
__global__ void fill_kernel(const int* __restrict__ rows, const int* __restrict__ cols,
                            int* __restrict__ cur, int* __restrict__ ecol)
{
    int i = blockIdx.x * blockDim.x + threadIdx.x;
    if (i >= K_REL * E_EDGES) return;
    int k = i / E_EDGES;
    int p = atomicAdd(&cur[k * N_NODES + rows[i]], 1);
    ecol[p] = cols[i];
}

// ================= gather =================
__global__ void gather_kernel(const int* __restrict__ off, const int* __restrict__ ecol,
                              const float* __restrict__ Z, float* __restrict__ Mb)
{
    int w = (blockIdx.x * blockDim.x + threadIdx.x) >> 5;
    int lane = threadIdx.x & 31;
    if (w >= NBUCKET) return;
    int k = w / N_NODES;
    int n = w - k * N_NODES;
    int s = off[w], t = off[w + 1];
    float4 a0 = make_float4(0.f, 0.f, 0.f, 0.f);
    float4 a1 = make_float4(0.f, 0.f, 0.f, 0.f);
    int e = s;
    for (; e + 2 <= t; e += 2) {
        int c0 = ecol[e], c1 = ecol[e + 1];
        float4 v0 = reinterpret_cast<const float4*>(Z + (size_t)c0 * DDIM)[lane];
        float4 v1 = reinterpret_cast<const float4*>(Z + (size_t)c1 * DDIM)[lane];
        a0.x += v0.x; a0.y += v0.y; a0.z += v0.z; a0.w += v0.w;
        a1.x += v1.x; a1.y += v1.y; a1.z += v1.z; a1.w += v1.w;
    }
    if (e < t) {
        int c0 = ecol[e];
        float4 v0 = reinterpret_cast<const float4*>(Z + (size_t)c0 * DDIM)[lane];
        a0.x += v0.x; a0.y += v0.y; a0.z += v0.z; a0.w += v0.w;
    }
    float4 r;
    r.x = fminf(fmaxf(a0.x + a1.x, -MCLAMP), MCLAMP);
    r.y = fminf(fmaxf(a0.y + a1.y, -MCLAMP), MCLAMP);
    r.z = fminf(fmaxf(a0.z + a1.z, -MCLAMP), MCLAMP);
    r.w = fminf(fmaxf(a0.w + a1.w, -MCLAMP), MCLAMP);
    reinterpret_cast<float4*>(Mb + ((size_t)n * K_REL + k) * DDIM)[lane] = r;
}

// ================= misc kernels =================
__global__ void zero_kernel(float* p, int n) {
    int i = blockIdx.x * blockDim.x + threadIdx.x;
    if (i < n) p[i] = 0.f;
}

__global__ void score_kernel(const float* __restrict__ G, const float* __restrict__ gateH,
                             const float* __restrict__ logdeg, const float* __restrict__ w_ld,
                             const float* __restrict__ bg1, const float* __restrict__ Wg2,
                             const float* __restrict__ bg2, float* __restrict__ scores)
{
    int warp = (blockIdx.x * blockDim.x + threadIdx.x) >> 5;
    int lane = threadIdx.x & 31;
    if (warp >= N_NODES * K_REL) return;
    int n = warp >> 2;
    float ld = logdeg[warp];
    float acc = 0.f;
#pragma unroll
    for (int i = 0; i < 4; i++) {
        int d = lane + i * 32;
        float v = G[(long long)warp * GATEH + d] + gateH[(long long)n * GATEH + d]
                + ld * w_ld[d] + bg1[d];
        v = fmaxf(v, 0.f);
        acc += v * Wg2[d];
    }
#pragma unroll
    for (int o = 16; o > 0; o >>= 1) acc += __shfl_xor_sync(0xFFFFFFFFu, acc, o);
    if (lane == 0) scores[warp] = acc + bg2[0];
}

__global__ void softmax_kernel(const float* __restrict__ scores, const float* __restrict__ mask,
                               float* __restrict__ alpha)
{
    int n = blockIdx.x * blockDim.x + threadIdx.x;
    if (n >= N_NODES) return;
    float s[K_REL], a[K_REL];
    float m = -1e30f;
#pragma unroll
    for (int k = 0; k < K_REL; k++) { s[k] = scores[n * K_REL + k] * TEMP_INV; m = fmaxf(m, s[k]); }
    float sum = 0.f;
#pragma unroll
    for (int k = 0; k < K_REL; k++) { a[k] = __expf(s[k] - m); sum += a[k]; }
    float inv = 1.f / sum;
    float sum2 = 0.f;
#pragma unroll
    for (int k = 0; k < K_REL; k++) { a[k] = a[k] * inv * mask[n * K_REL + k]; sum2 += a[k]; }
    float inv2 = 1.f / fmaxf(sum2, 1e-12f);
    float sum3 = 0.f;
#pragma unroll
    for (int k = 0; k < K_REL; k++) { a[k] = fmaxf(a[k] * inv2, 1e-8f); sum3 += a[k]; }
    float inv3 = 1.f / fmaxf(sum3, 1e-12f);
#pragma unroll
    for (int k = 0; k < K_REL; k++) alpha[n * K_REL + k] = a[k] * inv3;
}

// 16 nodes per block; register-accumulated colsum, 1 atomic per column per block
#define FUSE_NPB 16
__global__ __launch_bounds__(DDIM) void fused_kernel(
    const float* __restrict__ Mb, const float* __restrict__ alpha,
    const float* __restrict__ H, float* __restrict__ Xres, float* __restrict__ colsum)
{
    int d = threadIdx.x;
    int n0 = blockIdx.x * FUSE_NPB;
    __shared__ float a[FUSE_NPB][K_REL];
    __shared__ float wsum[4];
    if (d < FUSE_NPB * K_REL)
        a[d >> 2][d & 3] = alpha[n0 * K_REL + d];
    __syncthreads();
    float csum = 0.f, qsum = 0.f;
#pragma unroll
    for (int i = 0; i < FUSE_NPB; i++) {
        int n = n0 + i;
        if (n >= N_NODES) break;
        float f = 0.f;
#pragma unroll
        for (int k = 0; k < K_REL; k++)
            f += a[i][k] * Mb[((size_t)n * K_REL + k) * DDIM + d];
        float x = f + H[(size_t)n * DDIM + d];
        Xres[(size_t)n * DDIM + d] = x;
        csum += x;
        qsum += x * x;
    }
    atomicAdd(&colsum[d], csum);
#pragma unroll
    for (int o = 16; o > 0; o >>= 1) qsum += __shfl_xor_sync(0xFFFFFFFFu, qsum, o);
    if ((d & 31) == 0) wsum[d >> 5] = qsum;
    __syncthreads();
    if (d == 0) atomicAdd(&colsum[DDIM], wsum[0] + wsum[1] + wsum[2] + wsum[3]);
}

__global__ void stats_kernel(const float* __restrict__ colsum, float* __restrict__ stats)
{
    int d = threadIdx.x;
    __shared__ float wsum[4];
    float mu = colsum[d] * (1.0f / N_NODES);
    stats[d] = mu;
    float q = mu * mu;
#pragma unroll
    for (int o = 16; o > 0; o >>= 1) q += __shfl_xor_sync(0xFFFFFFFFu, q, o);
    if ((d & 31) == 0) wsum[d >> 5] = q;
    __syncthreads();
    if (d == 0) {
        float summu2 = wsum[0] + wsum[1] + wsum[2] + wsum[3];
        float var = (colsum[DDIM] - (float)N_NODES * summu2) * (1.0f / N_NODES);
        var = fmaxf(var, 0.f);
        stats[DDIM] = 1.0f / (sqrtf(var) + 1e-6f);
    }
}

__global__ void normalize_kernel(const float* __restrict__ Xres, const float* __restrict__ stats,
                                 float* __restrict__ H)
{
    int i = blockIdx.x * blockDim.x + threadIdx.x;
    if (i >= N_NODES * DDIM) return;
    int d = i & (DDIM - 1);
    float v = (Xres[i] - stats[d]) * stats[DDIM];
    H[i] = fmaxf(v, 0.f);
}

__global__ void logits_kernel(const float* __restrict__ hid, const float* __restrict__ Wh2,
                              const float* __restrict__ bh2, float* __restrict__ out)
{
    int warp = (blockIdx.x * blockDim.x + threadIdx.x) >> 5;
    int lane = threadIdx.x & 31;
    if (warp >= N_NODES) return;
    float acc = 0.f;
#pragma unroll
    for (int i = 0; i < 4; i++) {
        int d = lane + i * 32;
        acc += hid[(long long)warp * DDIM + d] * Wh2[d];
    }
#pragma unroll
    for (int o = 16; o > 0; o >>= 1) acc += __shfl_xor_sync(0xFFFFFFFFu, acc, o);
    if (lane == 0) out[warp] = acc + bh2[0];
}

__global__ void copy_alpha_kernel(const float* __restrict__ alpha, float* __restrict__ out,
                                  int out_size)
{
    int i = blockIdx.x * blockDim.x + threadIdx.x;
    if (i >= 2 * N_NODES * K_REL) return;
    if (N_NODES + i < out_size) out[N_NODES + i] = alpha[i];
}

// ================= host =================
extern "C" void kernel_launch(void* const* d_in, const int* in_sizes, int n_in,
                              void* d_out, int out_size)
{
    const float* X      = (const float*)d_in[0];
    const int*   rows   = (const int*)d_in[1];
    const int*   cols   = (const int*)d_in[2];
    const float* mask   = (const float*)d_in[3];
    const float* logdeg = (const float*)d_in[4];
    const float* W_in0  = (const float*)d_in[5];
    const float* b_in0  = (const float*)d_in[6];
    const float* W_in1  = (const float*)d_in[7];
    const float* b_in1  = (const float*)d_in[8];
    const float* W_in2  = (const float*)d_in[9];
    const float* b_in2  = (const float*)d_in[10];
    const float* Wmsg[2]  = {(const float*)d_in[11], (const float*)d_in[16]};
    const float* Wg1[2]   = {(const float*)d_in[12], (const float*)d_in[17]};
    const float* bg1[2]   = {(const float*)d_in[13], (const float*)d_in[18]};
    const float* Wg2[2]   = {(const float*)d_in[14], (const float*)d_in[19]};
    const float* bg2[2]   = {(const float*)d_in[15], (const float*)d_in[20]};
    const float* Wh1    = (const float*)d_in[21];
    const float* bh1    = (const float*)d_in[22];
    const float* Wh2    = (const float*)d_in[23];
    const float* bh2    = (const float*)d_in[24];
    float* out = (float*)d_out;

    float *buf0, *buf1, *H, *Z, *Mb, *gateH, *G, *scores, *alpha, *Xres, *hid, *colsum, *stats;
    float *Wt0, *Wt1, *Wt2, *WmT, *Wg1hT, *Wg1mT, *Wh1T;
    int *cnt, *off, *cur, *ecol, *bsum, *btop;
    cudaGetSymbolAddress((void**)&buf0,  g_buf0);
    cudaGetSymbolAddress((void**)&buf1,  g_buf1);
    cudaGetSymbolAddress((void**)&H,     g_H);
    cudaGetSymbolAddress((void**)&Z,     g_Z);
    cudaGetSymbolAddress((void**)&Mb,    g_M);
    cudaGetSymbolAddress((void**)&gateH, g_gateH);
    cudaGetSymbolAddress((void**)&G,     g_G);
    cudaGetSymbolAddress((void**)&scores,g_scores);
    cudaGetSymbolAddress((void**)&alpha, g_alpha);
    cudaGetSymbolAddress((void**)&Xres,  g_Xres);
    cudaGetSymbolAddress((void**)&hid,   g_hid);
    cudaGetSymbolAddress((void**)&colsum,g_colsum);
    cudaGetSymbolAddress((void**)&stats, g_stats);
    cudaGetSymbolAddress((void**)&cnt,   g_cnt);
    cudaGetSymbolAddress((void**)&off,   g_off);
    cudaGetSymbolAddress((void**)&cur,   g_cur);
    cudaGetSymbolAddress((void**)&ecol,  g_ecol);
    cudaGetSymbolAddress((void**)&bsum,  g_bsum);
    cudaGetSymbolAddress((void**)&btop,  g_btop);
    cudaGetSymbolAddress((void**)&Wt0,   g_Wt0);
    cudaGetSymbolAddress((void**)&Wt1,   g_Wt1);
    cudaGetSymbolAddress((void**)&Wt2,   g_Wt2);
    cudaGetSymbolAddress((void**)&WmT,   g_WmT);
    cudaGetSymbolAddress((void**)&Wg1hT, g_Wg1hT);
    cudaGetSymbolAddress((void**)&Wg1mT, g_Wg1mT);
    cudaGetSymbolAddress((void**)&Wh1T,  g_Wh1T);

    cudaFuncSetAttribute(mma_gemm<true,true>,   cudaFuncAttributeMaxDynamicSharedMemorySize, GEMM_SMEM);
    cudaFuncSetAttribute(mma_gemm<false,false>, cudaFuncAttributeMaxDynamicSharedMemorySize, GEMM_SMEM);

    TJobs jobs;
    jobs.j[0] = { W_in0, Wt0, INDIM, HINDIM };
    jobs.j[1] = { W_in1, Wt1, HINDIM, HINDIM };
    jobs.j[2] = { W_in2, Wt2, HINDIM, DDIM };
    jobs.j[3] = { Wmsg[0], WmT,                      DDIM, DDIM };
    jobs.j[4] = { Wg1[0],  Wg1hT,                    DDIM, GATEH };
    jobs.j[5] = { Wg1[0] + DDIM * GATEH, Wg1mT,      DDIM, GATEH };
    jobs.j[6] = { Wmsg[1], WmT + DDIM * DDIM,        DDIM, DDIM };
    jobs.j[7] = { Wg1[1],  Wg1hT + GATEH * DDIM,     DDIM, GATEH };
    jobs.j[8] = { Wg1[1] + DDIM * GATEH, Wg1mT + GATEH * DDIM, DDIM, GATEH };
    jobs.j[9] = { Wh1, Wh1T, DDIM, DDIM };

    const int MT = (N_NODES + 127) / 128;  // 157

    // 0-4: transposes + CSR phases A/B
    transpose_multi<<<dim3(8, 32, 10), dim3(32, 8)>>>(jobs);
    zero_int_kernel<<<(NBUCKET + 255) / 256, 256>>>(cnt, NBUCKET);
    hist_kernel<<<(K_REL * E_EDGES + 255) / 256, 256>>>(rows, cnt);
    scan_part<<<SCB, SCT>>>(cnt, bsum);
    scan_top<<<1, SCT>>>(bsum, btop, off);

    // 5 (profiled): big encoder GEMM
    mma_gemm<true,true><<<dim3(2, MT), 256, GEMM_SMEM>>>(X,    Wt0, b_in0, buf0, N_NODES, INDIM,  HINDIM);
    mma_gemm<true,true><<<dim3(2, MT), 256, GEMM_SMEM>>>(buf0, Wt1, b_in1, buf1, N_NODES, HINDIM, HINDIM);
    mma_gemm<true,true><<<dim3(1, MT), 256, GEMM_SMEM>>>(buf1, Wt2, b_in2, H,    N_NODES, HINDIM, DDIM);

    // CSR phase C + fill (needed before first gather)
    scan_write<<<SCB, SCT>>>(cnt, btop, off, cur);
    fill_kernel<<<(K_REL * E_EDGES + 255) / 256, 256>>>(rows, cols, cur, ecol);

    for (int b = 0; b < 2; b++) {
        mma_gemm<false,false><<<dim3(1, MT), 256, GEMM_SMEM>>>(H, WmT + b * DDIM * DDIM, nullptr, Z, N_NODES, DDIM, DDIM);
        gather_kernel<<<(NBUCKET * 32 + 255) / 256, 256>>>(off, ecol, Z, Mb);
        mma_gemm<false,false><<<dim3(1, MT), 256, GEMM_SMEM>>>(H, Wg1hT + b * GATEH * DDIM, nullptr, gateH, N_NODES, DDIM, GATEH);
        mma_gemm<false,false><<<dim3(1, 625), 256, GEMM_SMEM>>>(Mb, Wg1mT + b * GATEH * DDIM, nullptr, G, N_NODES * K_REL, DDIM, GATEH);
        score_kernel<<<(N_NODES * K_REL * 32 + 255) / 256, 256>>>(G, gateH, logdeg, Wg1[b] + 2 * DDIM * GATEH,
                                                                  bg1[b], Wg2[b], bg2[b], scores);
        softmax_kernel<<<(N_NODES + 255) / 256, 256>>>(scores, mask, alpha + b * N_NODES * K_REL);
        zero_kernel<<<1, 256>>>(colsum, DDIM + 1);
        fused_kernel<<<(N_NODES + FUSE_NPB - 1) / FUSE_NPB, DDIM>>>(Mb, alpha + b * N_NODES * K_REL, H, Xres, colsum);
        stats_kernel<<<1, DDIM>>>(colsum, stats);
        normalize_kernel<<<(N_NODES * DDIM + 255) / 256, 256>>>(Xres, stats, H);
    }

    mma_gemm<true,true><<<dim3(1, MT), 256, GEMM_SMEM>>>(H, Wh1T, bh1, hid, N_NODES, DDIM, DDIM);
    logits_kernel<<<(N_NODES * 32 + 255) / 256, 256>>>(hid, Wh2, bh2, out);
    copy_alpha_kernel<<<(2 * N_NODES * K_REL + 255) / 256, 256>>>(alpha, out, out_size);
}

// round 6
// speedup vs baseline: 2.3162x; 1.0341x over previous
#include <cuda_runtime.h>
#include <cuda_bf16.h>
#include <math.h>
#include <cstdint>

#define N_NODES 20000
#define K_REL   4
#define E_EDGES 320000
#define INDIM   1024
#define HINDIM  256
#define DDIM    128
#define GATEH   128
#define TEMP_INV (1.0f/0.6f)
#define MCLAMP  20.0f
#define NBUCKET (K_REL * N_NODES)

// ---------------- scratch (device globals; no allocation) ----------------
__device__ float g_buf0[N_NODES * HINDIM];
__device__ float g_buf1[N_NODES * HINDIM];
__device__ float g_H[N_NODES * DDIM];
__device__ float g_Z[N_NODES * DDIM];
__device__ float g_M[N_NODES * K_REL * DDIM];
__device__ float g_gateH[N_NODES * GATEH];
__device__ float g_G[N_NODES * K_REL * GATEH];
__device__ float g_scores[N_NODES * K_REL];
__device__ float g_alpha[2 * N_NODES * K_REL];
__device__ float g_Xres[N_NODES * DDIM];
__device__ float g_hid[N_NODES * DDIM];
__device__ float g_colsum[DDIM + 1];
__device__ float g_stats[DDIM + 1];
// CSR
__device__ int g_cnt[NBUCKET];
__device__ int g_off[NBUCKET + 1];
__device__ int g_cur[NBUCKET];
__device__ int g_ecol[K_REL * E_EDGES];
__device__ int g_bsum[256];
__device__ int g_btop[256];

// ================= helpers =================
__device__ __forceinline__ uint32_t smem_u32(const void* p) {
    uint32_t a;
    asm("{ .reg .u64 t; cvta.to.shared.u64 t, %1; cvt.u32.u64 %0, t; }" : "=r"(a) : "l"(p));
    return a;
}
__device__ __forceinline__ void ldsm_x4(uint32_t* r, uint32_t addr) {
    asm volatile("ldmatrix.sync.aligned.m8n8.x4.shared.b16 {%0,%1,%2,%3}, [%4];"
        : "=r"(r[0]), "=r"(r[1]), "=r"(r[2]), "=r"(r[3]) : "r"(addr));
}
__device__ __forceinline__ void ldsm_x4_t(uint32_t* r, uint32_t addr) {
    asm volatile("ldmatrix.sync.aligned.m8n8.x4.trans.shared.b16 {%0,%1,%2,%3}, [%4];"
        : "=r"(r[0]), "=r"(r[1]), "=r"(r[2]), "=r"(r[3]) : "r"(addr));
}
__device__ __forceinline__ void mma_bf16(float* c, const uint32_t* a, const uint32_t* b) {
    asm volatile("mma.sync.aligned.m16n8k16.row.col.f32.bf16.bf16.f32 "
        "{%0,%1,%2,%3}, {%4,%5,%6,%7}, {%8,%9}, {%0,%1,%2,%3};"
        : "+f"(c[0]), "+f"(c[1]), "+f"(c[2]), "+f"(c[3])
        : "r"(a[0]), "r"(a[1]), "r"(a[2]), "r"(a[3]), "r"(b[0]), "r"(b[1]));
}
__device__ __forceinline__ uint32_t pack_bf16(float a, float b) {
    __nv_bfloat162 h = __floats2bfloat162_rn(a, b);
    return *reinterpret_cast<uint32_t*>(&h);
}

// ================= bf16 3-split GEMM, B read in natural [K,N] layout =================
// C[M,N] = A[M,K] @ B[K,N] (+bias)(+relu). BM=BN=128, BK=32.
// A smem: [m][k] bf16, 80B rows. B smem: [k][n] bf16, 272B rows (trans-ldmatrix).
#define ROWB_A 80
#define ROWB_B 272
#define A_TILE (128 * ROWB_A)            // 10240
#define B_TILE (32 * ROWB_B)             // 8704
#define STAGE_B (2 * A_TILE + 2 * B_TILE)  // 37888
#define GEMM_SMEM (2 * STAGE_B)            // 75776
#define B_OFF (2 * A_TILE)               // B hi at stage+B_OFF, lo at +B_OFF+B_TILE

template <bool RELU, bool BIAS, bool DUAL>
__global__ __launch_bounds__(256) void mma_gemm(
    const float* __restrict__ A, const float* __restrict__ B1,
    const float* __restrict__ bias, float* __restrict__ C1,
    int M, int K, int N,
    const float* __restrict__ B2, float* __restrict__ C2)
{
    extern __shared__ __align__(128) char smem[];
    const int tid = threadIdx.x;
    const int lane = tid & 31;
    const int wid = tid >> 5;
    const int warp_m = wid & 3;
    const int warp_n = wid >> 2;
    const int rowBase = blockIdx.y * 128;
    const int nch = K >> 5;

    const float* Bp = B1;
    float* Cp = C1;
    int cb = blockIdx.x * 128;
    if (DUAL) {
        if (blockIdx.x == 1) { Bp = B2; Cp = C2; }
        cb = 0;
    }

    float acc[2][8][4];
#pragma unroll
    for (int i = 0; i < 2; i++)
#pragma unroll
        for (int j = 0; j < 8; j++)
#pragma unroll
            for (int q = 0; q < 4; q++) acc[i][j][q] = 0.f;

    const uint32_t sb = smem_u32(smem);
    // A fragment lane addressing (non-trans ldmatrix over [m][k] rows)
    const int aRow = warp_m * 32 + (lane & 7) + ((lane >> 3) & 1) * 8;
    const int aK   = ((lane >> 4) & 1) * 8;
    const uint32_t aBase = sb + (uint32_t)(aRow * ROWB_A + aK * 2);
    // B fragment lane addressing (trans ldmatrix over [k][n] rows)
    const uint32_t bBase = sb + (uint32_t)B_OFF
                         + (uint32_t)((lane & 15) * ROWB_B + (lane >> 4) * 16);

    float4 aR[4], bR[4];

    auto gload = [&](int c) {
        const int k0 = c << 5;
#pragma unroll
        for (int j = 0; j < 4; j++) {
            int idx = tid + j * 256;
            // A: 128 m-rows x 32 k
            int r = idx >> 3;
            int col = (idx & 7) * 4;
            int gr = rowBase + r;
            float4 v = make_float4(0.f, 0.f, 0.f, 0.f);
            if (gr < M) v = *reinterpret_cast<const float4*>(A + (size_t)gr * K + k0 + col);
            aR[j] = v;
            // B: 32 k-rows x 128 n
            int br = idx >> 5;
            int bcol = (idx & 31) * 4;
            bR[j] = *reinterpret_cast<const float4*>(Bp + (size_t)(k0 + br) * N + cb + bcol);
        }
    };
    auto sstore = [&](int s) {
        char* st = smem + s * STAGE_B;
#pragma unroll
        for (int j = 0; j < 4; j++) {
            int idx = tid + j * 256;
            // A
            int r = idx >> 3;
            int col = (idx & 7) * 4;
            int offA = r * ROWB_A + col * 2;
            float4 v = aR[j];
            float hx = __bfloat162float(__float2bfloat16(v.x));
            float hy = __bfloat162float(__float2bfloat16(v.y));
            float hz = __bfloat162float(__float2bfloat16(v.z));
            float hw = __bfloat162float(__float2bfloat16(v.w));
            *reinterpret_cast<uint2*>(st + offA) =
                make_uint2(pack_bf16(hx, hy), pack_bf16(hz, hw));
            *reinterpret_cast<uint2*>(st + A_TILE + offA) =
                make_uint2(pack_bf16(v.x - hx, v.y - hy), pack_bf16(v.z - hz, v.w - hw));
            // B
            int br = idx >> 5;
            int bcol = (idx & 31) * 4;
            int offB = B_OFF + br * ROWB_B + bcol * 2;
            float4 w = bR[j];
            float gx = __bfloat162float(__float2bfloat16(w.x));
            float gy = __bfloat162float(__float2bfloat16(w.y));
            float gz = __bfloat162float(__float2bfloat16(w.z));
            float gw = __bfloat162float(__float2bfloat16(w.w));
            *reinterpret_cast<uint2*>(st + offB) =
                make_uint2(pack_bf16(gx, gy), pack_bf16(gz, gw));
            *reinterpret_cast<uint2*>(st + B_TILE + offB) =
                make_uint2(pack_bf16(w.x - gx, w.y - gy), pack_bf16(w.z - gz, w.w - gw));
        }
    };

    gload(0);
    sstore(0);
    __syncthreads();

    for (int c = 0; c < nch; c++) {
        const int s = c & 1;
        const uint32_t stoff = (uint32_t)s * STAGE_B;
        if (c + 1 < nch) gload(c + 1);

#pragma unroll
        for (int ks = 0; ks < 2; ks++) {
            uint32_t ah[2][4], al[2][4], bh[4][4], bl[4][4];
#pragma unroll
            for (int mt = 0; mt < 2; mt++) {
                ldsm_x4(ah[mt], aBase + stoff + mt * 16 * ROWB_A + ks * 32);
                ldsm_x4(al[mt], aBase + stoff + A_TILE + mt * 16 * ROWB_A + ks * 32);
            }
            // B: per nq (16-n group), trans load k16 x n16 (hi and lo)
#pragma unroll
            for (int nq = 0; nq < 4; nq++) {
                uint32_t ad = bBase + stoff + ks * 16 * ROWB_B
                            + (uint32_t)((warp_n * 64 + nq * 16) * 2);
                ldsm_x4_t(bh[nq], ad);
                ldsm_x4_t(bl[nq], ad + B_TILE);
            }
#pragma unroll
            for (int mt = 0; mt < 2; mt++) {
#pragma unroll
                for (int nt = 0; nt < 8; nt++) {
                    const uint32_t* bhp = &bh[nt >> 1][(nt & 1) * 2];
                    const uint32_t* blp = &bl[nt >> 1][(nt & 1) * 2];
                    mma_bf16(acc[mt][nt], ah[mt], bhp);
                    mma_bf16(acc[mt][nt], ah[mt], blp);
                    mma_bf16(acc[mt][nt], al[mt], bhp);
                }
            }
        }
        if (c + 1 < nch) sstore((c + 1) & 1);
        __syncthreads();
    }

    const int g = lane >> 2;
    const int tc2 = (lane & 3) * 2;
#pragma unroll
    for (int mt = 0; mt < 2; mt++) {
#pragma unroll
        for (int nt = 0; nt < 8; nt++) {
            int row0 = rowBase + warp_m * 32 + mt * 16 + g;
            int col = cb + warp_n * 64 + nt * 8 + tc2;
            float c0 = acc[mt][nt][0], c1 = acc[mt][nt][1];
            float c2 = acc[mt][nt][2], c3 = acc[mt][nt][3];
            if (BIAS) {
                float2 bb = *reinterpret_cast<const float2*>(bias + col);
                c0 += bb.x; c1 += bb.y; c2 += bb.x; c3 += bb.y;
            }
            if (RELU) {
                c0 = fmaxf(c0, 0.f); c1 = fmaxf(c1, 0.f);
                c2 = fmaxf(c2, 0.f); c3 = fmaxf(c3, 0.f);
            }
            if (row0 < M)
                *reinterpret_cast<float2*>(Cp + (size_t)row0 * N + col) = make_float2(c0, c1);
            if (row0 + 8 < M)
                *reinterpret_cast<float2*>(Cp + (size_t)(row0 + 8) * N + col) = make_float2(c2, c3);
        }
    }
}

// ================= CSR build =================
#define SCB 160
#define SCT 256
#define SPT 2

__global__ void zero_int_kernel(int* p, int n) {
    int i = blockIdx.x * blockDim.x + threadIdx.x;
    if (i < n) p[i] = 0;
}
__global__ void hist_kernel(const int* __restrict__ rows, int* __restrict__ cnt) {
    int i = blockIdx.x * blockDim.x + threadIdx.x;
    if (i >= K_REL * E_EDGES) return;
    int k = i / E_EDGES;
    atomicAdd(&cnt[k * N_NODES + rows[i]], 1);
}
__global__ __launch_bounds__(SCT) void scan_part(const int* __restrict__ cnt, int* __restrict__ bsum)
{
    __shared__ int ss[SCT];
    int b = blockIdx.x, t = threadIdx.x;
    int base = b * SCT * SPT + t * SPT;
    int local = 0;
#pragma unroll
    for (int i = 0; i < SPT; i++) {
        int idx = base + i;
        if (idx < NBUCKET) local += cnt[idx];
    }
    ss[t] = local; __syncthreads();
    for (int d = SCT >> 1; d > 0; d >>= 1) {
        if (t < d) ss[t] += ss[t + d];
        __syncthreads();
    }
    if (t == 0) bsum[b] = ss[0];
}
__global__ __launch_bounds__(SCT) void scan_top(const int* __restrict__ bsum,
                                                int* __restrict__ btop, int* __restrict__ off)
{
    __shared__ int ss[SCT];
    int t = threadIdx.x;
    int v = (t < SCB) ? bsum[t] : 0;
    ss[t] = v; __syncthreads();
    for (int d = 1; d < SCT; d <<= 1) {
        int u = (t >= d) ? ss[t - d] : 0;
        __syncthreads();
        ss[t] += u;
        __syncthreads();
    }
    if (t < SCB) btop[t] = ss[t] - v;
    if (t == SCB - 1) off[NBUCKET] = ss[t];
}
__global__ __launch_bounds__(SCT) void scan_write(const int* __restrict__ cnt,
                                                  const int* __restrict__ btop,
                                                  int* __restrict__ off, int* __restrict__ cur)
{
    __shared__ int ss[SCT];
    int b = blockIdx.x, t = threadIdx.x;
    int base = b * SCT * SPT + t * SPT;
    int c[SPT];
    int local = 0;
#pragma unroll
    for (int i = 0; i < SPT; i++) {
        int idx = base + i;
        c[i] = (idx < NBUCKET) ? cnt[idx] : 0;
        local += c[i];
    }
    ss[t] = local; __syncthreads();
    for (int d = 1; d < SCT; d <<= 1) {
        int u = (t >= d) ? ss[t - d] : 0;
        __syncthreads();
        ss[t] += u;
        __syncthreads();
    }
    int run = btop[b] + ss[t] - local;
#pragma unroll
    for (int i = 0; i < SPT; i++) {
        int idx = base + i;
        if (idx < NBUCKET) { off[idx] = run; cur[idx] = run; run += c[i]; }
    }
}
__global__ void fill_kernel(const int* __restrict__ rows, const int* __restrict__ cols,
                            int* __restrict__ cur, int* __restrict__ ecol)
{
    int i = blockIdx.x * blockDim.x + threadIdx.x;
    if (i >= K_REL * E_EDGES) return;
    int k = i / E_EDGES;
    int p = atomicAdd(&cur[k * N_NODES + rows[i]], 1);
    ecol[p] = cols[i];
}

// ================= gather =================
__global__ void gather_kernel(const int* __restrict__ off, const int* __restrict__ ecol,
                              const float* __restrict__ Z, float* __restrict__ Mb)
{
    int w = (blockIdx.x * blockDim.x + threadIdx.x) >> 5;
    int lane = threadIdx.x & 31;
    if (w >= NBUCKET) return;
    int k = w / N_NODES;
    int n = w - k * N_NODES;
    int s = off[w], t = off[w + 1];
    float4 a0 = make_float4(0.f, 0.f, 0.f, 0.f);
    float4 a1 = make_float4(0.f, 0.f, 0.f, 0.f);
    int e = s;
    for (; e + 2 <= t; e += 2) {
        int c0 = ecol[e], c1 = ecol[e + 1];
        float4 v0 = reinterpret_cast<const float4*>(Z + (size_t)c0 * DDIM)[lane];
        float4 v1 = reinterpret_cast<const float4*>(Z + (size_t)c1 * DDIM)[lane];
        a0.x += v0.x; a0.y += v0.y; a0.z += v0.z; a0.w += v0.w;
        a1.x += v1.x; a1.y += v1.y; a1.z += v1.z; a1.w += v1.w;
    }
    if (e < t) {
        int c0 = ecol[e];
        float4 v0 = reinterpret_cast<const float4*>(Z + (size_t)c0 * DDIM)[lane];
        a0.x += v0.x; a0.y += v0.y; a0.z += v0.z; a0.w += v0.w;
    }
    float4 r;
    r.x = fminf(fmaxf(a0.x + a1.x, -MCLAMP), MCLAMP);
    r.y = fminf(fmaxf(a0.y + a1.y, -MCLAMP), MCLAMP);
    r.z = fminf(fmaxf(a0.z + a1.z, -MCLAMP), MCLAMP);
    r.w = fminf(fmaxf(a0.w + a1.w, -MCLAMP), MCLAMP);
    reinterpret_cast<float4*>(Mb + ((size_t)n * K_REL + k) * DDIM)[lane] = r;
}

// ================= misc kernels =================
__global__ void zero_kernel(float* p, int n) {
    int i = blockIdx.x * blockDim.x + threadIdx.x;
    if (i < n) p[i] = 0.f;
}

__global__ void score_kernel(const float* __restrict__ G, const float* __restrict__ gateH,
                             const float* __restrict__ logdeg, const float* __restrict__ w_ld,
                             const float* __restrict__ bg1, const float* __restrict__ Wg2,
                             const float* __restrict__ bg2, float* __restrict__ scores)
{
    int warp = (blockIdx.x * blockDim.x + threadIdx.x) >> 5;
    int lane = threadIdx.x & 31;
    if (warp >= N_NODES * K_REL) return;
    int n = warp >> 2;
    float ld = logdeg[warp];
    float acc = 0.f;
#pragma unroll
    for (int i = 0; i < 4; i++) {
        int d = lane + i * 32;
        float v = G[(long long)warp * GATEH + d] + gateH[(long long)n * GATEH + d]
                + ld * w_ld[d] + bg1[d];
        v = fmaxf(v, 0.f);
        acc += v * Wg2[d];
    }
#pragma unroll
    for (int o = 16; o > 0; o >>= 1) acc += __shfl_xor_sync(0xFFFFFFFFu, acc, o);
    if (lane == 0) scores[warp] = acc + bg2[0];
}

__global__ void softmax_kernel(const float* __restrict__ scores, const float* __restrict__ mask,
                               float* __restrict__ alpha)
{
    int n = blockIdx.x * blockDim.x + threadIdx.x;
    if (n >= N_NODES) return;
    float s[K_REL], a[K_REL];
    float m = -1e30f;
#pragma unroll
    for (int k = 0; k < K_REL; k++) { s[k] = scores[n * K_REL + k] * TEMP_INV; m = fmaxf(m, s[k]); }
    float sum = 0.f;
#pragma unroll
    for (int k = 0; k < K_REL; k++) { a[k] = __expf(s[k] - m); sum += a[k]; }
    float inv = 1.f / sum;
    float sum2 = 0.f;
#pragma unroll
    for (int k = 0; k < K_REL; k++) { a[k] = a[k] * inv * mask[n * K_REL + k]; sum2 += a[k]; }
    float inv2 = 1.f / fmaxf(sum2, 1e-12f);
    float sum3 = 0.f;
#pragma unroll
    for (int k = 0; k < K_REL; k++) { a[k] = fmaxf(a[k] * inv2, 1e-8f); sum3 += a[k]; }
    float inv3 = 1.f / fmaxf(sum3, 1e-12f);
#pragma unroll
    for (int k = 0; k < K_REL; k++) alpha[n * K_REL + k] = a[k] * inv3;
}

#define FUSE_NPB 16
__global__ __launch_bounds__(DDIM) void fused_kernel(
    const float* __restrict__ Mb, const float* __restrict__ alpha,
    const float* __restrict__ H, float* __restrict__ Xres, float* __restrict__ colsum)
{
    int d = threadIdx.x;
    int n0 = blockIdx.x * FUSE_NPB;
    __shared__ float a[FUSE_NPB][K_REL];
    __shared__ float wsum[4];
    if (d < FUSE_NPB * K_REL)
        a[d >> 2][d & 3] = alpha[n0 * K_REL + d];
    __syncthreads();
    float csum = 0.f, qsum = 0.f;
#pragma unroll
    for (int i = 0; i < FUSE_NPB; i++) {
        int n = n0 + i;
        if (n >= N_NODES) break;
        float f = 0.f;
#pragma unroll
        for (int k = 0; k < K_REL; k++)
            f += a[i][k] * Mb[((size_t)n * K_REL + k) * DDIM + d];
        float x = f + H[(size_t)n * DDIM + d];
        Xres[(size_t)n * DDIM + d] = x;
        csum += x;
        qsum += x * x;
    }
    atomicAdd(&colsum[d], csum);
#pragma unroll
    for (int o = 16; o > 0; o >>= 1) qsum += __shfl_xor_sync(0xFFFFFFFFu, qsum, o);
    if ((d & 31) == 0) wsum[d >> 5] = qsum;
    __syncthreads();
    if (d == 0) atomicAdd(&colsum[DDIM], wsum[0] + wsum[1] + wsum[2] + wsum[3]);
}

__global__ void stats_kernel(const float* __restrict__ colsum, float* __restrict__ stats)
{
    int d = threadIdx.x;
    __shared__ float wsum[4];
    float mu = colsum[d] * (1.0f / N_NODES);
    stats[d] = mu;
    float q = mu * mu;
#pragma unroll
    for (int o = 16; o > 0; o >>= 1) q += __shfl_xor_sync(0xFFFFFFFFu, q, o);
    if ((d & 31) == 0) wsum[d >> 5] = q;
    __syncthreads();
    if (d == 0) {
        float summu2 = wsum[0] + wsum[1] + wsum[2] + wsum[3];
        float var = (colsum[DDIM] - (float)N_NODES * summu2) * (1.0f / N_NODES);
        var = fmaxf(var, 0.f);
        stats[DDIM] = 1.0f / (sqrtf(var) + 1e-6f);
    }
}

__global__ void normalize_kernel(const float* __restrict__ Xres, const float* __restrict__ stats,
                                 float* __restrict__ H)
{
    int i = blockIdx.x * blockDim.x + threadIdx.x;
    if (i >= N_NODES * DDIM) return;
    int d = i & (DDIM - 1);
    float v = (Xres[i] - stats[d]) * stats[DDIM];
    H[i] = fmaxf(v, 0.f);
}

__global__ void logits_kernel(const float* __restrict__ hid, const float* __restrict__ Wh2,
                              const float* __restrict__ bh2, float* __restrict__ out)
{
    int warp = (blockIdx.x * blockDim.x + threadIdx.x) >> 5;
    int lane = threadIdx.x & 31;
    if (warp >= N_NODES) return;
    float acc = 0.f;
#pragma unroll
    for (int i = 0; i < 4; i++) {
        int d = lane + i * 32;
        acc += hid[(long long)warp * DDIM + d] * Wh2[d];
    }
#pragma unroll
    for (int o = 16; o > 0; o >>= 1) acc += __shfl_xor_sync(0xFFFFFFFFu, acc, o);
    if (lane == 0) out[warp] = acc + bh2[0];
}

__global__ void copy_alpha_kernel(const float* __restrict__ alpha, float* __restrict__ out,
                                  int out_size)
{
    int i = blockIdx.x * blockDim.x + threadIdx.x;
    if (i >= 2 * N_NODES * K_REL) return;
    if (N_NODES + i < out_size) out[N_NODES + i] = alpha[i];
}

// ================= host =================
extern "C" void kernel_launch(void* const* d_in, const int* in_sizes, int n_in,
                              void* d_out, int out_size)
{
    const float* X      = (const float*)d_in[0];
    const int*   rows   = (const int*)d_in[1];
    const int*   cols   = (const int*)d_in[2];
    const float* mask   = (const float*)d_in[3];
    const float* logdeg = (const float*)d_in[4];
    const float* W_in0  = (const float*)d_in[5];
    const float* b_in0  = (const float*)d_in[6];
    const float* W_in1  = (const float*)d_in[7];
    const float* b_in1  = (const float*)d_in[8];
    const float* W_in2  = (const float*)d_in[9];
    const float* b_in2  = (const float*)d_in[10];
    const float* Wmsg[2]  = {(const float*)d_in[11], (const float*)d_in[16]};
    const float* Wg1[2]   = {(const float*)d_in[12], (const float*)d_in[17]};
    const float* bg1[2]   = {(const float*)d_in[13], (const float*)d_in[18]};
    const float* Wg2[2]   = {(const float*)d_in[14], (const float*)d_in[19]};
    const float* bg2[2]   = {(const float*)d_in[15], (const float*)d_in[20]};
    const float* Wh1    = (const float*)d_in[21];
    const float* bh1    = (const float*)d_in[22];
    const float* Wh2    = (const float*)d_in[23];
    const float* bh2    = (const float*)d_in[24];
    float* out = (float*)d_out;

    float *buf0, *buf1, *H, *Z, *Mb, *gateH, *G, *scores, *alpha, *Xres, *hid, *colsum, *stats;
    int *cnt, *off, *cur, *ecol, *bsum, *btop;
    cudaGetSymbolAddress((void**)&buf0,  g_buf0);
    cudaGetSymbolAddress((void**)&buf1,  g_buf1);
    cudaGetSymbolAddress((void**)&H,     g_H);
    cudaGetSymbolAddress((void**)&Z,     g_Z);
    cudaGetSymbolAddress((void**)&Mb,    g_M);
    cudaGetSymbolAddress((void**)&gateH, g_gateH);
    cudaGetSymbolAddress((void**)&G,     g_G);
    cudaGetSymbolAddress((void**)&scores,g_scores);
    cudaGetSymbolAddress((void**)&alpha, g_alpha);
    cudaGetSymbolAddress((void**)&Xres,  g_Xres);
    cudaGetSymbolAddress((void**)&hid,   g_hid);
    cudaGetSymbolAddress((void**)&colsum,g_colsum);
    cudaGetSymbolAddress((void**)&stats, g_stats);
    cudaGetSymbolAddress((void**)&cnt,   g_cnt);
    cudaGetSymbolAddress((void**)&off,   g_off);
    cudaGetSymbolAddress((void**)&cur,   g_cur);
    cudaGetSymbolAddress((void**)&ecol,  g_ecol);
    cudaGetSymbolAddress((void**)&bsum,  g_bsum);
    cudaGetSymbolAddress((void**)&btop,  g_btop);

    cudaFuncSetAttribute(mma_gemm<true,true,false>,   cudaFuncAttributeMaxDynamicSharedMemorySize, GEMM_SMEM);
    cudaFuncSetAttribute(mma_gemm<false,false,false>, cudaFuncAttributeMaxDynamicSharedMemorySize, GEMM_SMEM);
    cudaFuncSetAttribute(mma_gemm<false,false,true>,  cudaFuncAttributeMaxDynamicSharedMemorySize, GEMM_SMEM);

    const int MT = (N_NODES + 127) / 128;  // 157

    // 0-2: CSR front half (independent of GEMMs)
    zero_int_kernel<<<(NBUCKET + 255) / 256, 256>>>(cnt, NBUCKET);
    hist_kernel<<<(K_REL * E_EDGES + 255) / 256, 256>>>(rows, cnt);
    scan_part<<<SCB, SCT>>>(cnt, bsum);

    // 3 (profiled): encoder GEMM 1 (the heavyweight)
    mma_gemm<true,true,false><<<dim3(2, MT), 256, GEMM_SMEM>>>(X, W_in0, b_in0, buf0,
        N_NODES, INDIM, HINDIM, nullptr, nullptr);

    // 4-6: CSR back half
    scan_top<<<1, SCT>>>(bsum, btop, off);
    scan_write<<<SCB, SCT>>>(cnt, btop, off, cur);
    fill_kernel<<<(K_REL * E_EDGES + 255) / 256, 256>>>(rows, cols, cur, ecol);

    // 7-8: encoder GEMMs 2-3
    mma_gemm<true,true,false><<<dim3(2, MT), 256, GEMM_SMEM>>>(buf0, W_in1, b_in1, buf1,
        N_NODES, HINDIM, HINDIM, nullptr, nullptr);
    mma_gemm<true,true,false><<<dim3(1, MT), 256, GEMM_SMEM>>>(buf1, W_in2, b_in2, H,
        N_NODES, HINDIM, DDIM, nullptr, nullptr);

    for (int b = 0; b < 2; b++) {
        // Z = H@Wmsg and gateH = H@Wg1[0:128] in ONE launch
        mma_gemm<false,false,true><<<dim3(2, MT), 256, GEMM_SMEM>>>(H, Wmsg[b], nullptr, Z,
            N_NODES, DDIM, DDIM, Wg1[b], gateH);
        gather_kernel<<<(NBUCKET * 32 + 255) / 256, 256>>>(off, ecol, Z, Mb);
        mma_gemm<false,false,false><<<dim3(1, 625), 256, GEMM_SMEM>>>(Mb, Wg1[b] + DDIM * GATEH, nullptr, G,
            N_NODES * K_REL, DDIM, GATEH, nullptr, nullptr);
        score_kernel<<<(N_NODES * K_REL * 32 + 255) / 256, 256>>>(G, gateH, logdeg, Wg1[b] + 2 * DDIM * GATEH,
                                                                  bg1[b], Wg2[b], bg2[b], scores);
        softmax_kernel<<<(N_NODES + 255) / 256, 256>>>(scores, mask, alpha + b * N_NODES * K_REL);
        zero_kernel<<<1, 256>>>(colsum, DDIM + 1);
        fused_kernel<<<(N_NODES + FUSE_NPB - 1) / FUSE_NPB, DDIM>>>(Mb, alpha + b * N_NODES * K_REL, H, Xres, colsum);
        stats_kernel<<<1, DDIM>>>(colsum, stats);
        normalize_kernel<<<(N_NODES * DDIM + 255) / 256, 256>>>(Xres, stats, H);
    }

    mma_gemm<true,true,false><<<dim3(1, MT), 256, GEMM_SMEM>>>(H, Wh1, bh1, hid,
        N_NODES, DDIM, DDIM, nullptr, nullptr);
    logits_kernel<<<(N_NODES * 32 + 255) / 256, 256>>>(hid, Wh2, bh2, out);
    copy_alpha_kernel<<<(2 * N_NODES * K_REL + 255) / 256, 256>>>(alpha, out, out_size);
}

// round 7
// speedup vs baseline: 2.3569x; 1.0176x over previous
#include <cuda_runtime.h>
#include <cuda_bf16.h>
#include <math.h>
#include <cstdint>

#define N_NODES 20000
#define K_REL   4
#define E_EDGES 320000
#define INDIM   1024
#define HINDIM  256
#define DDIM    128
#define GATEH   128
#define TEMP_INV (1.0f/0.6f)
#define MCLAMP  20.0f
#define NBUCKET (K_REL * N_NODES)

// ---------------- scratch (device globals; no allocation) ----------------
__device__ float g_buf0[N_NODES * HINDIM];
__device__ float g_buf1[N_NODES * HINDIM];
__device__ float g_H[N_NODES * DDIM];
__device__ float g_Z[N_NODES * DDIM];
__device__ float g_M[N_NODES * K_REL * DDIM];
__device__ float g_gateH[N_NODES * GATEH];
__device__ float g_G[N_NODES * K_REL * GATEH];
__device__ float g_scores[N_NODES * K_REL];
__device__ float g_alpha[2 * N_NODES * K_REL];
__device__ float g_Xres[N_NODES * DDIM];
__device__ float g_hid[N_NODES * DDIM];
__device__ float g_colsum[DDIM + 1];
__device__ float g_stats[DDIM + 1];
// CSR
__device__ int g_cnt[NBUCKET];
__device__ int g_off[NBUCKET + 1];
__device__ int g_cur[NBUCKET];
__device__ int g_ecol[K_REL * E_EDGES];
__device__ int g_bsum[256];
__device__ int g_btop[256];

// ================= helpers =================
__device__ __forceinline__ uint32_t smem_u32(const void* p) {
    uint32_t a;
    asm("{ .reg .u64 t; cvta.to.shared.u64 t, %1; cvt.u32.u64 %0, t; }" : "=r"(a) : "l"(p));
    return a;
}
__device__ __forceinline__ void ldsm_x4(uint32_t* r, uint32_t addr) {
    asm volatile("ldmatrix.sync.aligned.m8n8.x4.shared.b16 {%0,%1,%2,%3}, [%4];"
        : "=r"(r[0]), "=r"(r[1]), "=r"(r[2]), "=r"(r[3]) : "r"(addr));
}
__device__ __forceinline__ void ldsm_x4_t(uint32_t* r, uint32_t addr) {
    asm volatile("ldmatrix.sync.aligned.m8n8.x4.trans.shared.b16 {%0,%1,%2,%3}, [%4];"
        : "=r"(r[0]), "=r"(r[1]), "=r"(r[2]), "=r"(r[3]) : "r"(addr));
}
__device__ __forceinline__ void mma_bf16(float* c, const uint32_t* a, const uint32_t* b) {
    asm volatile("mma.sync.aligned.m16n8k16.row.col.f32.bf16.bf16.f32 "
        "{%0,%1,%2,%3}, {%4,%5,%6,%7}, {%8,%9}, {%0,%1,%2,%3};"
        : "+f"(c[0]), "+f"(c[1]), "+f"(c[2]), "+f"(c[3])
        : "r"(a[0]), "r"(a[1]), "r"(a[2]), "r"(a[3]), "r"(b[0]), "r"(b[1]));
}
__device__ __forceinline__ uint32_t pack_bf16(float a, float b) {
    __nv_bfloat162 h = __floats2bfloat162_rn(a, b);
    return *reinterpret_cast<uint32_t*>(&h);
}

// ================= bf16 3-split GEMM, 512 threads, warp tile 32x32 =================
// C[M,N] = A[M,K] @ B[K,N] (+bias)(+relu). BM=BN=128, BK=32.
// A smem: [m][k] bf16, 80B rows. B smem: [k][n] bf16, 272B rows (trans-ldmatrix).
#define GT 512
#define ROWB_A 80
#define ROWB_B 272
#define A_TILE (128 * ROWB_A)              // 10240
#define B_TILE (32 * ROWB_B)               // 8704
#define STAGE_B (2 * A_TILE + 2 * B_TILE)  // 37888
#define GEMM_SMEM (2 * STAGE_B)            // 75776
#define B_OFF (2 * A_TILE)

template <bool RELU, bool BIAS, bool DUAL>
__global__ __launch_bounds__(GT) void mma_gemm(
    const float* __restrict__ A, const float* __restrict__ B1,
    const float* __restrict__ bias, float* __restrict__ C1,
    int M, int K, int N,
    const float* __restrict__ B2, float* __restrict__ C2)
{
    extern __shared__ __align__(128) char smem[];
    const int tid = threadIdx.x;
    const int lane = tid & 31;
    const int wid = tid >> 5;
    const int warp_m = wid & 3;        // 4 groups x 32 rows
    const int warp_n = wid >> 2;       // 4 groups x 32 cols
    const int rowBase = blockIdx.y * 128;
    const int nch = K >> 5;

    const float* Bp = B1;
    float* Cp = C1;
    int cb = blockIdx.x * 128;
    if (DUAL) {
        if (blockIdx.x == 1) { Bp = B2; Cp = C2; }
        cb = 0;
    }

    float acc[2][4][4];
#pragma unroll
    for (int i = 0; i < 2; i++)
#pragma unroll
        for (int j = 0; j < 4; j++)
#pragma unroll
            for (int q = 0; q < 4; q++) acc[i][j][q] = 0.f;

    const uint32_t sb = smem_u32(smem);
    const int aRow = warp_m * 32 + (lane & 7) + ((lane >> 3) & 1) * 8;
    const int aK   = ((lane >> 4) & 1) * 8;
    const uint32_t aBase = sb + (uint32_t)(aRow * ROWB_A + aK * 2);
    const uint32_t bBase = sb + (uint32_t)B_OFF
                         + (uint32_t)((lane & 15) * ROWB_B + (lane >> 4) * 16);

    float4 aR[2], bR[2];

    auto gload = [&](int c) {
        const int k0 = c << 5;
#pragma unroll
        for (int j = 0; j < 2; j++) {
            int idx = tid + j * GT;
            int r = idx >> 3;
            int col = (idx & 7) * 4;
            int gr = rowBase + r;
            float4 v = make_float4(0.f, 0.f, 0.f, 0.f);
            if (gr < M) v = *reinterpret_cast<const float4*>(A + (size_t)gr * K + k0 + col);
            aR[j] = v;
            int br = idx >> 5;
            int bcol = (idx & 31) * 4;
            bR[j] = *reinterpret_cast<const float4*>(Bp + (size_t)(k0 + br) * N + cb + bcol);
        }
    };
    auto sstore = [&](int s) {
        char* st = smem + s * STAGE_B;
#pragma unroll
        for (int j = 0; j < 2; j++) {
            int idx = tid + j * GT;
            int r = idx >> 3;
            int col = (idx & 7) * 4;
            int offA = r * ROWB_A + col * 2;
            float4 v = aR[j];
            float hx = __bfloat162float(__float2bfloat16(v.x));
            float hy = __bfloat162float(__float2bfloat16(v.y));
            float hz = __bfloat162float(__float2bfloat16(v.z));
            float hw = __bfloat162float(__float2bfloat16(v.w));
            *reinterpret_cast<uint2*>(st + offA) =
                make_uint2(pack_bf16(hx, hy), pack_bf16(hz, hw));
            *reinterpret_cast<uint2*>(st + A_TILE + offA) =
                make_uint2(pack_bf16(v.x - hx, v.y - hy), pack_bf16(v.z - hz, v.w - hw));
            int br = idx >> 5;
            int bcol = (idx & 31) * 4;
            int offB = B_OFF + br * ROWB_B + bcol * 2;
            float4 w = bR[j];
            float gx = __bfloat162float(__float2bfloat16(w.x));
            float gy = __bfloat162float(__float2bfloat16(w.y));
            float gz = __bfloat162float(__float2bfloat16(w.z));
            float gw = __bfloat162float(__float2bfloat16(w.w));
            *reinterpret_cast<uint2*>(st + offB) =
                make_uint2(pack_bf16(gx, gy), pack_bf16(gz, gw));
            *reinterpret_cast<uint2*>(st + B_TILE + offB) =
                make_uint2(pack_bf16(w.x - gx, w.y - gy), pack_bf16(w.z - gz, w.w - gw));
        }
    };

    gload(0);
    sstore(0);
    __syncthreads();

    for (int c = 0; c < nch; c++) {
        const int s = c & 1;
        const uint32_t stoff = (uint32_t)s * STAGE_B;
        if (c + 1 < nch) gload(c + 1);

#pragma unroll
        for (int ks = 0; ks < 2; ks++) {
            uint32_t ah[2][4], al[2][4], bh[2][4], bl[2][4];
#pragma unroll
            for (int mt = 0; mt < 2; mt++) {
                ldsm_x4(ah[mt], aBase + stoff + mt * 16 * ROWB_A + ks * 32);
                ldsm_x4(al[mt], aBase + stoff + A_TILE + mt * 16 * ROWB_A + ks * 32);
            }
#pragma unroll
            for (int nq = 0; nq < 2; nq++) {
                uint32_t ad = bBase + stoff + ks * 16 * ROWB_B
                            + (uint32_t)((warp_n * 32 + nq * 16) * 2);
                ldsm_x4_t(bh[nq], ad);
                ldsm_x4_t(bl[nq], ad + B_TILE);
            }
#pragma unroll
            for (int mt = 0; mt < 2; mt++) {
#pragma unroll
                for (int nt = 0; nt < 4; nt++) {
                    const uint32_t* bhp = &bh[nt >> 1][(nt & 1) * 2];
                    const uint32_t* blp = &bl[nt >> 1][(nt & 1) * 2];
                    mma_bf16(acc[mt][nt], ah[mt], bhp);
                    mma_bf16(acc[mt][nt], ah[mt], blp);
                    mma_bf16(acc[mt][nt], al[mt], bhp);
                }
            }
        }
        if (c + 1 < nch) sstore((c + 1) & 1);
        __syncthreads();
    }

    const int g = lane >> 2;
    const int tc2 = (lane & 3) * 2;
#pragma unroll
    for (int mt = 0; mt < 2; mt++) {
#pragma unroll
        for (int nt = 0; nt < 4; nt++) {
            int row0 = rowBase + warp_m * 32 + mt * 16 + g;
            int col = cb + warp_n * 32 + nt * 8 + tc2;
            float c0 = acc[mt][nt][0], c1 = acc[mt][nt][1];
            float c2 = acc[mt][nt][2], c3 = acc[mt][nt][3];
            if (BIAS) {
                float2 bb = *reinterpret_cast<const float2*>(bias + col);
                c0 += bb.x; c1 += bb.y; c2 += bb.x; c3 += bb.y;
            }
            if (RELU) {
                c0 = fmaxf(c0, 0.f); c1 = fmaxf(c1, 0.f);
                c2 = fmaxf(c2, 0.f); c3 = fmaxf(c3, 0.f);
            }
            if (row0 < M)
                *reinterpret_cast<float2*>(Cp + (size_t)row0 * N + col) = make_float2(c0, c1);
            if (row0 + 8 < M)
                *reinterpret_cast<float2*>(Cp + (size_t)(row0 + 8) * N + col) = make_float2(c2, c3);
        }
    }
}

// ================= CSR build =================
#define SCB 160
#define SCT 256
#define SPT 2

__global__ void zero_int_kernel(int* p, int n) {
    int i = blockIdx.x * blockDim.x + threadIdx.x;
    if (i < n) p[i] = 0;
}
__global__ void hist_kernel(const int* __restrict__ rows, int* __restrict__ cnt) {
    int i = blockIdx.x * blockDim.x + threadIdx.x;
    if (i >= K_REL * E_EDGES) return;
    int k = i / E_EDGES;
    atomicAdd(&cnt[k * N_NODES + rows[i]], 1);
}
__global__ __launch_bounds__(SCT) void scan_part(const int* __restrict__ cnt, int* __restrict__ bsum)
{
    __shared__ int ss[SCT];
    int b = blockIdx.x, t = threadIdx.x;
    int base = b * SCT * SPT + t * SPT;
    int local = 0;
#pragma unroll
    for (int i = 0; i < SPT; i++) {
        int idx = base + i;
        if (idx < NBUCKET) local += cnt[idx];
    }
    ss[t] = local; __syncthreads();
    for (int d = SCT >> 1; d > 0; d >>= 1) {
        if (t < d) ss[t] += ss[t + d];
        __syncthreads();
    }
    if (t == 0) bsum[b] = ss[0];
}
__global__ __launch_bounds__(SCT) void scan_top(const int* __restrict__ bsum,
                                                int* __restrict__ btop, int* __restrict__ off)
{
    __shared__ int ss[SCT];
    int t = threadIdx.x;
    int v = (t < SCB) ? bsum[t] : 0;
    ss[t] = v; __syncthreads();
    for (int d = 1; d < SCT; d <<= 1) {
        int u = (t >= d) ? ss[t - d] : 0;
        __syncthreads();
        ss[t] += u;
        __syncthreads();
    }
    if (t < SCB) btop[t] = ss[t] - v;
    if (t == SCB - 1) off[NBUCKET] = ss[t];
}
__global__ __launch_bounds__(SCT) void scan_write(const int* __restrict__ cnt,
                                                  const int* __restrict__ btop,
                                                  int* __restrict__ off, int* __restrict__ cur)
{
    __shared__ int ss[SCT];
    int b = blockIdx.x, t = threadIdx.x;
    int base = b * SCT * SPT + t * SPT;
    int c[SPT];
    int local = 0;
#pragma unroll
    for (int i = 0; i < SPT; i++) {
        int idx = base + i;
        c[i] = (idx < NBUCKET) ? cnt[idx] : 0;
        local += c[i];
    }
    ss[t] = local; __syncthreads();
    for (int d = 1; d < SCT; d <<= 1) {
        int u = (t >= d) ? ss[t - d] : 0;
        __syncthreads();
        ss[t] += u;
        __syncthreads();
    }
    int run = btop[b] + ss[t] - local;
#pragma unroll
    for (int i = 0; i < SPT; i++) {
        int idx = base + i;
        if (idx < NBUCKET) { off[idx] = run; cur[idx] = run; run += c[i]; }
    }
}
__global__ void fill_kernel(const int* __restrict__ rows, const int* __restrict__ cols,
                            int* __restrict__ cur, int* __restrict__ ecol)
{
    int i = blockIdx.x * blockDim.x + threadIdx.x;
    if (i >= K_REL * E_EDGES) return;
    int k = i / E_EDGES;
    int p = atomicAdd(&cur[k * N_NODES + rows[i]], 1);
    ecol[p] = cols[i];
}

// ================= gather =================
__global__ void gather_kernel(const int* __restrict__ off, const int* __restrict__ ecol,
                              const float* __restrict__ Z, float* __restrict__ Mb)
{
    int w = (blockIdx.x * blockDim.x + threadIdx.x) >> 5;
    int lane = threadIdx.x & 31;
    if (w >= NBUCKET) return;
    int k = w / N_NODES;
    int n = w - k * N_NODES;
    int s = off[w], t = off[w + 1];
    float4 a0 = make_float4(0.f, 0.f, 0.f, 0.f);
    float4 a1 = make_float4(0.f, 0.f, 0.f, 0.f);
    int e = s;
    for (; e + 2 <= t; e += 2) {
        int c0 = ecol[e], c1 = ecol[e + 1];
        float4 v0 = reinterpret_cast<const float4*>(Z + (size_t)c0 * DDIM)[lane];
        float4 v1 = reinterpret_cast<const float4*>(Z + (size_t)c1 * DDIM)[lane];
        a0.x += v0.x; a0.y += v0.y; a0.z += v0.z; a0.w += v0.w;
        a1.x += v1.x; a1.y += v1.y; a1.z += v1.z; a1.w += v1.w;
    }
    if (e < t) {
        int c0 = ecol[e];
        float4 v0 = reinterpret_cast<const float4*>(Z + (size_t)c0 * DDIM)[lane];
        a0.x += v0.x; a0.y += v0.y; a0.z += v0.z; a0.w += v0.w;
    }
    float4 r;
    r.x = fminf(fmaxf(a0.x + a1.x, -MCLAMP), MCLAMP);
    r.y = fminf(fmaxf(a0.y + a1.y, -MCLAMP), MCLAMP);
    r.z = fminf(fmaxf(a0.z + a1.z, -MCLAMP), MCLAMP);
    r.w = fminf(fmaxf(a0.w + a1.w, -MCLAMP), MCLAMP);
    reinterpret_cast<float4*>(Mb + ((size_t)n * K_REL + k) * DDIM)[lane] = r;
}

// ================= misc kernels =================
__global__ void zero_kernel(float* p, int n) {
    int i = blockIdx.x * blockDim.x + threadIdx.x;
    if (i < n) p[i] = 0.f;
}

__global__ void score_kernel(const float* __restrict__ G, const float* __restrict__ gateH,
                             const float* __restrict__ logdeg, const float* __restrict__ w_ld,
                             const float* __restrict__ bg1, const float* __restrict__ Wg2,
                             const float* __restrict__ bg2, float* __restrict__ scores)
{
    int warp = (blockIdx.x * blockDim.x + threadIdx.x) >> 5;
    int lane = threadIdx.x & 31;
    if (warp >= N_NODES * K_REL) return;
    int n = warp >> 2;
    float ld = logdeg[warp];
    float acc = 0.f;
#pragma unroll
    for (int i = 0; i < 4; i++) {
        int d = lane + i * 32;
        float v = G[(long long)warp * GATEH + d] + gateH[(long long)n * GATEH + d]
                + ld * w_ld[d] + bg1[d];
        v = fmaxf(v, 0.f);
        acc += v * Wg2[d];
    }
#pragma unroll
    for (int o = 16; o > 0; o >>= 1) acc += __shfl_xor_sync(0xFFFFFFFFu, acc, o);
    if (lane == 0) scores[warp] = acc + bg2[0];
}

__global__ void softmax_kernel(const float* __restrict__ scores, const float* __restrict__ mask,
                               float* __restrict__ alpha)
{
    int n = blockIdx.x * blockDim.x + threadIdx.x;
    if (n >= N_NODES) return;
    float s[K_REL], a[K_REL];
    float m = -1e30f;
#pragma unroll
    for (int k = 0; k < K_REL; k++) { s[k] = scores[n * K_REL + k] * TEMP_INV; m = fmaxf(m, s[k]); }
    float sum = 0.f;
#pragma unroll
    for (int k = 0; k < K_REL; k++) { a[k] = __expf(s[k] - m); sum += a[k]; }
    float inv = 1.f / sum;
    float sum2 = 0.f;
#pragma unroll
    for (int k = 0; k < K_REL; k++) { a[k] = a[k] * inv * mask[n * K_REL + k]; sum2 += a[k]; }
    float inv2 = 1.f / fmaxf(sum2, 1e-12f);
    float sum3 = 0.f;
#pragma unroll
    for (int k = 0; k < K_REL; k++) { a[k] = fmaxf(a[k] * inv2, 1e-8f); sum3 += a[k]; }
    float inv3 = 1.f / fmaxf(sum3, 1e-12f);
#pragma unroll
    for (int k = 0; k < K_REL; k++) alpha[n * K_REL + k] = a[k] * inv3;
}

#define FUSE_NPB 16
__global__ __launch_bounds__(DDIM) void fused_kernel(
    const float* __restrict__ Mb, const float* __restrict__ alpha,
    const float* __restrict__ H, float* __restrict__ Xres, float* __restrict__ colsum)
{
    int d = threadIdx.x;
    int n0 = blockIdx.x * FUSE_NPB;
    __shared__ float a[FUSE_NPB][K_REL];
    __shared__ float wsum[4];
    if (d < FUSE_NPB * K_REL)
        a[d >> 2][d & 3] = alpha[n0 * K_REL + d];
    __syncthreads();
    float csum = 0.f, qsum = 0.f;
#pragma unroll
    for (int i = 0; i < FUSE_NPB; i++) {
        int n = n0 + i;
        if (n >= N_NODES) break;
        float f = 0.f;
#pragma unroll
        for (int k = 0; k < K_REL; k++)
            f += a[i][k] * Mb[((size_t)n * K_REL + k) * DDIM + d];
        float x = f + H[(size_t)n * DDIM + d];
        Xres[(size_t)n * DDIM + d] = x;
        csum += x;
        qsum += x * x;
    }
    atomicAdd(&colsum[d], csum);
#pragma unroll
    for (int o = 16; o > 0; o >>= 1) qsum += __shfl_xor_sync(0xFFFFFFFFu, qsum, o);
    if ((d & 31) == 0) wsum[d >> 5] = qsum;
    __syncthreads();
    if (d == 0) atomicAdd(&colsum[DDIM], wsum[0] + wsum[1] + wsum[2] + wsum[3]);
}

__global__ void stats_kernel(const float* __restrict__ colsum, float* __restrict__ stats)
{
    int d = threadIdx.x;
    __shared__ float wsum[4];
    float mu = colsum[d] * (1.0f / N_NODES);
    stats[d] = mu;
    float q = mu * mu;
#pragma unroll
    for (int o = 16; o > 0; o >>= 1) q += __shfl_xor_sync(0xFFFFFFFFu, q, o);
    if ((d & 31) == 0) wsum[d >> 5] = q;
    __syncthreads();
    if (d == 0) {
        float summu2 = wsum[0] + wsum[1] + wsum[2] + wsum[3];
        float var = (colsum[DDIM] - (float)N_NODES * summu2) * (1.0f / N_NODES);
        var = fmaxf(var, 0.f);
        stats[DDIM] = 1.0f / (sqrtf(var) + 1e-6f);
    }
}

__global__ void normalize_kernel(const float* __restrict__ Xres, const float* __restrict__ stats,
                                 float* __restrict__ H)
{
    int i = blockIdx.x * blockDim.x + threadIdx.x;
    if (i >= N_NODES * DDIM) return;
    int d = i & (DDIM - 1);
    float v = (Xres[i] - stats[d]) * stats[DDIM];
    H[i] = fmaxf(v, 0.f);
}

__global__ void logits_kernel(const float* __restrict__ hid, const float* __restrict__ Wh2,
                              const float* __restrict__ bh2, float* __restrict__ out)
{
    int warp = (blockIdx.x * blockDim.x + threadIdx.x) >> 5;
    int lane = threadIdx.x & 31;
    if (warp >= N_NODES) return;
    float acc = 0.f;
#pragma unroll
    for (int i = 0; i < 4; i++) {
        int d = lane + i * 32;
        acc += hid[(long long)warp * DDIM + d] * Wh2[d];
    }
#pragma unroll
    for (int o = 16; o > 0; o >>= 1) acc += __shfl_xor_sync(0xFFFFFFFFu, acc, o);
    if (lane == 0) out[warp] = acc + bh2[0];
}

__global__ void copy_alpha_kernel(const float* __restrict__ alpha, float* __restrict__ out,
                                  int out_size)
{
    int i = blockIdx.x * blockDim.x + threadIdx.x;
    if (i >= 2 * N_NODES * K_REL) return;
    if (N_NODES + i < out_size) out[N_NODES + i] = alpha[i];
}

// ================= host =================
extern "C" void kernel_launch(void* const* d_in, const int* in_sizes, int n_in,
                              void* d_out, int out_size)
{
    const float* X      = (const float*)d_in[0];
    const int*   rows   = (const int*)d_in[1];
    const int*   cols   = (const int*)d_in[2];
    const float* mask   = (const float*)d_in[3];
    const float* logdeg = (const float*)d_in[4];
    const float* W_in0  = (const float*)d_in[5];
    const float* b_in0  = (const float*)d_in[6];
    const float* W_in1  = (const float*)d_in[7];
    const float* b_in1  = (const float*)d_in[8];
    const float* W_in2  = (const float*)d_in[9];
    const float* b_in2  = (const float*)d_in[10];
    const float* Wmsg[2]  = {(const float*)d_in[11], (const float*)d_in[16]};
    const float* Wg1[2]   = {(const float*)d_in[12], (const float*)d_in[17]};
    const float* bg1[2]   = {(const float*)d_in[13], (const float*)d_in[18]};
    const float* Wg2[2]   = {(const float*)d_in[14], (const float*)d_in[19]};
    const float* bg2[2]   = {(const float*)d_in[15], (const float*)d_in[20]};
    const float* Wh1    = (const float*)d_in[21];
    const float* bh1    = (const float*)d_in[22];
    const float* Wh2    = (const float*)d_in[23];
    const float* bh2    = (const float*)d_in[24];
    float* out = (float*)d_out;

    float *buf0, *buf1, *H, *Z, *Mb, *gateH, *G, *scores, *alpha, *Xres, *hid, *colsum, *stats;
    int *cnt, *off, *cur, *ecol, *bsum, *btop;
    cudaGetSymbolAddress((void**)&buf0,  g_buf0);
    cudaGetSymbolAddress((void**)&buf1,  g_buf1);
    cudaGetSymbolAddress((void**)&H,     g_H);
    cudaGetSymbolAddress((void**)&Z,     g_Z);
    cudaGetSymbolAddress((void**)&Mb,    g_M);
    cudaGetSymbolAddress((void**)&gateH, g_gateH);
    cudaGetSymbolAddress((void**)&G,     g_G);
    cudaGetSymbolAddress((void**)&scores,g_scores);
    cudaGetSymbolAddress((void**)&alpha, g_alpha);
    cudaGetSymbolAddress((void**)&Xres,  g_Xres);
    cudaGetSymbolAddress((void**)&hid,   g_hid);
    cudaGetSymbolAddress((void**)&colsum,g_colsum);
    cudaGetSymbolAddress((void**)&stats, g_stats);
    cudaGetSymbolAddress((void**)&cnt,   g_cnt);
    cudaGetSymbolAddress((void**)&off,   g_off);
    cudaGetSymbolAddress((void**)&cur,   g_cur);
    cudaGetSymbolAddress((void**)&ecol,  g_ecol);
    cudaGetSymbolAddress((void**)&bsum,  g_bsum);
    cudaGetSymbolAddress((void**)&btop,  g_btop);

    cudaFuncSetAttribute(mma_gemm<true,true,false>,   cudaFuncAttributeMaxDynamicSharedMemorySize, GEMM_SMEM);
    cudaFuncSetAttribute(mma_gemm<false,false,false>, cudaFuncAttributeMaxDynamicSharedMemorySize, GEMM_SMEM);
    cudaFuncSetAttribute(mma_gemm<false,false,true>,  cudaFuncAttributeMaxDynamicSharedMemorySize, GEMM_SMEM);

    const int MT = (N_NODES + 127) / 128;  // 157

    // 0-2: CSR front half
    zero_int_kernel<<<(NBUCKET + 255) / 256, 256>>>(cnt, NBUCKET);
    hist_kernel<<<(K_REL * E_EDGES + 255) / 256, 256>>>(rows, cnt);
    scan_part<<<SCB, SCT>>>(cnt, bsum);

    // 3 (profiled): encoder GEMM 1
    mma_gemm<true,true,false><<<dim3(2, MT), GT, GEMM_SMEM>>>(X, W_in0, b_in0, buf0,
        N_NODES, INDIM, HINDIM, nullptr, nullptr);

    // 4-6: CSR back half
    scan_top<<<1, SCT>>>(bsum, btop, off);
    scan_write<<<SCB, SCT>>>(cnt, btop, off, cur);
    fill_kernel<<<(K_REL * E_EDGES + 255) / 256, 256>>>(rows, cols, cur, ecol);

    // 7-8: encoder GEMMs 2-3
    mma_gemm<true,true,false><<<dim3(2, MT), GT, GEMM_SMEM>>>(buf0, W_in1, b_in1, buf1,
        N_NODES, HINDIM, HINDIM, nullptr, nullptr);
    mma_gemm<true,true,false><<<dim3(1, MT), GT, GEMM_SMEM>>>(buf1, W_in2, b_in2, H,
        N_NODES, HINDIM, DDIM, nullptr, nullptr);

    for (int b = 0; b < 2; b++) {
        mma_gemm<false,false,true><<<dim3(2, MT), GT, GEMM_SMEM>>>(H, Wmsg[b], nullptr, Z,
            N_NODES, DDIM, DDIM, Wg1[b], gateH);
        gather_kernel<<<(NBUCKET * 32 + 255) / 256, 256>>>(off, ecol, Z, Mb);
        mma_gemm<false,false,false><<<dim3(1, 625), GT, GEMM_SMEM>>>(Mb, Wg1[b] + DDIM * GATEH, nullptr, G,
            N_NODES * K_REL, DDIM, GATEH, nullptr, nullptr);
        score_kernel<<<(N_NODES * K_REL * 32 + 255) / 256, 256>>>(G, gateH, logdeg, Wg1[b] + 2 * DDIM * GATEH,
                                                                  bg1[b], Wg2[b], bg2[b], scores);
        softmax_kernel<<<(N_NODES + 255) / 256, 256>>>(scores, mask, alpha + b * N_NODES * K_REL);
        zero_kernel<<<1, 256>>>(colsum, DDIM + 1);
        fused_kernel<<<(N_NODES + FUSE_NPB - 1) / FUSE_NPB, DDIM>>>(Mb, alpha + b * N_NODES * K_REL, H, Xres, colsum);
        stats_kernel<<<1, DDIM>>>(colsum, stats);
        normalize_kernel<<<(N_NODES * DDIM + 255) / 256, 256>>>(Xres, stats, H);
    }

    mma_gemm<true,true,false><<<dim3(1, MT), GT, GEMM_SMEM>>>(H, Wh1, bh1, hid,
        N_NODES, DDIM, DDIM, nullptr, nullptr);
    logits_kernel<<<(N_NODES * 32 + 255) / 256, 256>>>(hid, Wh2, bh2, out);
    copy_alpha_kernel<<<(2 * N_NODES * K_REL + 255) / 256, 256>>>(alpha, out, out_size);
}